// round 3
// baseline (speedup 1.0000x reference)
#include <cuda_runtime.h>
#include <math.h>

// Problem constants
#define BATCH 2
#define T_SEQ 2048
#define CDIM  1024
#define NH    16
#define HS    64
#define QKV_ELEMS (BATCH * NH * T_SEQ * HS)   // 4 M floats = 16 MB each

// -2/1024 * ln(10000)
#define ROPE_COEF (-0.017988211f)

// Scratch (device globals — no allocation allowed in kernel_launch)
__device__ float g_q[QKV_ELEMS];
__device__ float g_k[QKV_ELEMS];
__device__ float g_v[QKV_ELEMS];

// ---------------------------------------------------------------------------
// Kernel A: out = x @ W^T (fp32 tiled GEMM), fused RoPE epilogue for Q/K,
// writes to scratch in [B, H, T, HS] layout.
// Grid: (CDIM/64, (B*T)/64, 3), Block: 256 threads
// ---------------------------------------------------------------------------
#define BM 64
#define BN 64
#define BK 16

__global__ __launch_bounds__(256) void qkv_gemm_rope(
    const float* __restrict__ x,
    const float* __restrict__ Wq,
    const float* __restrict__ Wk,
    const float* __restrict__ Wv)
{
    __shared__ float As[BK][BM + 4];   // +4 keeps float4 smem reads 16B-aligned
    __shared__ float Bs[BK][BN + 4];

    const int z = blockIdx.z;
    const float* __restrict__ W = (z == 0) ? Wq : ((z == 1) ? Wk : Wv);
    float* __restrict__ out = (z == 0) ? g_q : ((z == 1) ? g_k : g_v);

    const int m0 = blockIdx.y * BM;
    const int n0 = blockIdx.x * BN;
    const int tid = threadIdx.x;
    const int tx = tid & 15;    // 0..15 (cols)
    const int ty = tid >> 4;    // 0..15 (rows)

    // Loader mapping: each thread loads one float4 per tile
    const int lr = tid >> 2;         // 0..63 row-in-tile
    const int lc = (tid & 3) * 4;    // 0,4,8,12 col-in-BK

    float acc[4][4];
#pragma unroll
    for (int r = 0; r < 4; r++)
#pragma unroll
        for (int c = 0; c < 4; c++) acc[r][c] = 0.f;

    const float* xrow = x + (size_t)(m0 + lr) * CDIM + lc;
    const float* wrow = W + (size_t)(n0 + lr) * CDIM + lc;

    for (int k0 = 0; k0 < CDIM; k0 += BK) {
        float4 av = *(const float4*)(xrow + k0);
        float4 bv = *(const float4*)(wrow + k0);
        __syncthreads();
        As[lc + 0][lr] = av.x; As[lc + 1][lr] = av.y;
        As[lc + 2][lr] = av.z; As[lc + 3][lr] = av.w;
        Bs[lc + 0][lr] = bv.x; Bs[lc + 1][lr] = bv.y;
        Bs[lc + 2][lr] = bv.z; Bs[lc + 3][lr] = bv.w;
        __syncthreads();
#pragma unroll
        for (int k = 0; k < BK; k++) {
            float4 a = *(const float4*)&As[k][ty * 4];
            float4 b = *(const float4*)&Bs[k][tx * 4];
            float aa[4] = {a.x, a.y, a.z, a.w};
            float bb[4] = {b.x, b.y, b.z, b.w};
#pragma unroll
            for (int r = 0; r < 4; r++)
#pragma unroll
                for (int c = 0; c < 4; c++)
                    acc[r][c] += aa[r] * bb[c];
        }
    }

    // Epilogue: write to [B, H, T, HS] layout, applying RoPE for z<2.
    const int mrow0 = m0 + ty * 4;           // 4 consecutive rows (same batch)
    const int b = mrow0 / T_SEQ;
#pragma unroll
    for (int cp = 0; cp < 4; cp += 2) {
        const int n = n0 + tx * 4 + cp;      // even column (pair start)
        const int h = n >> 6;
        const int d = n & 63;
        const int i = d >> 1;
        float theta = 0.f;
        if (z < 2) theta = expf((float)i * ROPE_COEF);
#pragma unroll
        for (int r = 0; r < 4; r++) {
            const int m = mrow0 + r;
            const int t = m & (T_SEQ - 1);
            const size_t base = (((size_t)(b * NH + h) * T_SEQ) + t) * HS + d;
            float v0 = acc[r][cp];
            float v1 = acc[r][cp + 1];
            if (z < 2) {
                // Accurate range reduction (fast-math-proof): reduce in double
                float ang = (float)t * theta;
                double da = (double)ang;
                double red = da - 6.283185307179586 * floor(da * 0.15915494309189535);
                float ar = (float)red;
                float sn, cs;
                sincosf(ar, &sn, &cs);
                float r0 = v0 * cs - v1 * sn;
                float r1 = v1 * cs + v0 * sn;
                out[base]     = r0;
                out[base + 1] = r1;
            } else {
                out[base]     = v0;
                out[base + 1] = v1;
            }
        }
    }
}

// ---------------------------------------------------------------------------
// Kernel B: causal flash attention, fp32, warp-per-query, online softmax.
// Grid: (T/8, B*H), Block: 256 threads (8 warps = 8 queries)
//
// Smem rows padded to 68 floats (272 B): float4 rows stay 16B-aligned, and
// bank(lane, d) = (4*lane + d) mod 32 -> conflict-free within each 8-lane
// phase of an LDS.128, and conflict-free for the scalar PV reads
// Vs[j][lane] / Vs[j][lane+32].
// ---------------------------------------------------------------------------
#define QB 8
#define KB 32
#define KPAD 68

__global__ __launch_bounds__(256) void flash_attn(float* __restrict__ out)
{
    __shared__ float Qs[QB][KPAD];
    __shared__ float Ks[KB][KPAD];
    __shared__ float Vs[KB][KPAD];

    const int bh = blockIdx.y;                 // 0..31  (b*NH + h)
    const int q0 = blockIdx.x * QB;
    const int tid = threadIdx.x;
    const int w = tid >> 5;                    // warp id = local query
    const int lane = tid & 31;

    const float* __restrict__ qp = g_q + (size_t)bh * T_SEQ * HS;
    const float* __restrict__ kp = g_k + (size_t)bh * T_SEQ * HS;
    const float* __restrict__ vp = g_v + (size_t)bh * T_SEQ * HS;

    // Load 8 query rows
    for (int idx = tid; idx < QB * HS; idx += 256)
        Qs[idx >> 6][idx & 63] = qp[(size_t)(q0 + (idx >> 6)) * HS + (idx & 63)];

    const int t = q0 + w;                      // this warp's query index
    float mM = -INFINITY, l = 0.f, acc0 = 0.f, acc1 = 0.f;

    const int kend = ((q0 + QB - 1) / KB + 1) * KB;   // causal bound (tile-rounded)
    for (int kt = 0; kt < kend; kt += KB) {
        __syncthreads();
        // 256 threads load 32x64 K and V: thread -> (row = tid>>3, d4 = (tid&7)*8)
        {
            const int r = tid >> 3;
            const int d = (tid & 7) * 8;
            const size_t g = (size_t)(kt + r) * HS + d;
            float4 k0v = *(const float4*)(kp + g);
            float4 k1v = *(const float4*)(kp + g + 4);
            float4 v0v = *(const float4*)(vp + g);
            float4 v1v = *(const float4*)(vp + g + 4);
            *(float4*)&Ks[r][d]     = k0v;
            *(float4*)&Ks[r][d + 4] = k1v;
            *(float4*)&Vs[r][d]     = v0v;
            *(float4*)&Vs[r][d + 4] = v1v;
        }
        __syncthreads();

        // Lane j owns key kt+j: full 64-dim dot product, float4 smem reads
        float s = 0.f;
#pragma unroll
        for (int d = 0; d < HS; d += 4) {
            float4 qv = *(const float4*)&Qs[w][d];
            float4 kv = *(const float4*)&Ks[lane][d];
            s += qv.x * kv.x + qv.y * kv.y + qv.z * kv.z + qv.w * kv.w;
        }
        s *= 0.03125f;                                  // 1024^-0.5
        if (kt + lane > t) s = -INFINITY;               // causal mask

        // Online softmax (all-lanes-broadcast reductions)
        float mt = s;
#pragma unroll
        for (int o = 16; o; o >>= 1)
            mt = fmaxf(mt, __shfl_xor_sync(0xffffffffu, mt, o));
        const float mnew = fmaxf(mM, mt);
        const float alpha = expf(mM - mnew);            // 0 on first tile
        const float p = expf(s - mnew);                 // 0 for masked lanes
        float ps = p;
#pragma unroll
        for (int o = 16; o; o >>= 1)
            ps += __shfl_xor_sync(0xffffffffu, ps, o);
        l = l * alpha + ps;
        acc0 *= alpha;
        acc1 *= alpha;

        // PV: broadcast p_j; lane holds output dims lane and lane+32
#pragma unroll
        for (int j = 0; j < KB; j++) {
            const float pj = __shfl_sync(0xffffffffu, p, j);
            acc0 += pj * Vs[j][lane];
            acc1 += pj * Vs[j][lane + 32];
        }
        mM = mnew;
    }

    const float inv = 1.f / l;
    const int b = bh >> 4;
    const int h = bh & 15;
    const size_t o = ((size_t)(b * T_SEQ + t)) * CDIM + h * HS + lane;
    out[o]      = acc0 * inv;
    out[o + 32] = acc1 * inv;
}

// ---------------------------------------------------------------------------
extern "C" void kernel_launch(void* const* d_in, const int* in_sizes, int n_in,
                              void* d_out, int out_size)
{
    const float* x  = (const float*)d_in[0];
    const float* Wq = (const float*)d_in[1];
    const float* Wk = (const float*)d_in[2];
    const float* Wv = (const float*)d_in[3];
    float* out = (float*)d_out;

    dim3 ggrid(CDIM / BN, (BATCH * T_SEQ) / BM, 3);
    qkv_gemm_rope<<<ggrid, 256>>>(x, Wq, Wk, Wv);

    dim3 fgrid(T_SEQ / QB, BATCH * NH);
    flash_attn<<<fgrid, 256>>>(out);
}

// round 4
// speedup vs baseline: 1.8231x; 1.8231x over previous
#include <cuda_runtime.h>
#include <math.h>

// Problem constants
#define BATCH 2
#define T_SEQ 2048
#define CDIM  1024
#define NH    16
#define HS    64
#define QKV_ELEMS (BATCH * NH * T_SEQ * HS)   // 4 M floats = 16 MB each

// -2/1024 * ln(10000)
#define ROPE_COEF (-0.017988211f)

// Scratch (device globals — no allocation allowed in kernel_launch)
__device__ float g_q[QKV_ELEMS];
__device__ float g_k[QKV_ELEMS];
__device__ float g_v[QKV_ELEMS];

// ---------------------------------------------------------------------------
// Kernel A: out = x @ W^T (fp32 tiled GEMM), fused RoPE epilogue for Q/K,
// writes to scratch in [B, H, T, HS] layout.  (unchanged from R2)
// ---------------------------------------------------------------------------
#define BM 64
#define BN 64
#define BK 16

__global__ __launch_bounds__(256) void qkv_gemm_rope(
    const float* __restrict__ x,
    const float* __restrict__ Wq,
    const float* __restrict__ Wk,
    const float* __restrict__ Wv)
{
    __shared__ float As[BK][BM + 4];
    __shared__ float Bs[BK][BN + 4];

    const int z = blockIdx.z;
    const float* __restrict__ W = (z == 0) ? Wq : ((z == 1) ? Wk : Wv);
    float* __restrict__ out = (z == 0) ? g_q : ((z == 1) ? g_k : g_v);

    const int m0 = blockIdx.y * BM;
    const int n0 = blockIdx.x * BN;
    const int tid = threadIdx.x;
    const int tx = tid & 15;
    const int ty = tid >> 4;

    const int lr = tid >> 2;
    const int lc = (tid & 3) * 4;

    float acc[4][4];
#pragma unroll
    for (int r = 0; r < 4; r++)
#pragma unroll
        for (int c = 0; c < 4; c++) acc[r][c] = 0.f;

    const float* xrow = x + (size_t)(m0 + lr) * CDIM + lc;
    const float* wrow = W + (size_t)(n0 + lr) * CDIM + lc;

    for (int k0 = 0; k0 < CDIM; k0 += BK) {
        float4 av = *(const float4*)(xrow + k0);
        float4 bv = *(const float4*)(wrow + k0);
        __syncthreads();
        As[lc + 0][lr] = av.x; As[lc + 1][lr] = av.y;
        As[lc + 2][lr] = av.z; As[lc + 3][lr] = av.w;
        Bs[lc + 0][lr] = bv.x; Bs[lc + 1][lr] = bv.y;
        Bs[lc + 2][lr] = bv.z; Bs[lc + 3][lr] = bv.w;
        __syncthreads();
#pragma unroll
        for (int k = 0; k < BK; k++) {
            float4 a = *(const float4*)&As[k][ty * 4];
            float4 b = *(const float4*)&Bs[k][tx * 4];
            float aa[4] = {a.x, a.y, a.z, a.w};
            float bb[4] = {b.x, b.y, b.z, b.w};
#pragma unroll
            for (int r = 0; r < 4; r++)
#pragma unroll
                for (int c = 0; c < 4; c++)
                    acc[r][c] += aa[r] * bb[c];
        }
    }

    const int mrow0 = m0 + ty * 4;
    const int b = mrow0 / T_SEQ;
#pragma unroll
    for (int cp = 0; cp < 4; cp += 2) {
        const int n = n0 + tx * 4 + cp;
        const int h = n >> 6;
        const int d = n & 63;
        const int i = d >> 1;
        float theta = 0.f;
        if (z < 2) theta = expf((float)i * ROPE_COEF);
#pragma unroll
        for (int r = 0; r < 4; r++) {
            const int m = mrow0 + r;
            const int t = m & (T_SEQ - 1);
            const size_t base = (((size_t)(b * NH + h) * T_SEQ) + t) * HS + d;
            float v0 = acc[r][cp];
            float v1 = acc[r][cp + 1];
            if (z < 2) {
                float ang = (float)t * theta;
                double da = (double)ang;
                double red = da - 6.283185307179586 * floor(da * 0.15915494309189535);
                float ar = (float)red;
                float sn, cs;
                sincosf(ar, &sn, &cs);
                out[base]     = v0 * cs - v1 * sn;
                out[base + 1] = v1 * cs + v0 * sn;
            } else {
                out[base]     = v0;
                out[base + 1] = v1;
            }
        }
    }
}

// ---------------------------------------------------------------------------
// Kernel B: register-tiled causal flash attention.
// Block = 64 queries of one (b,h); 16x16 threads; 4x4 micro-tile per thread.
// K tiles of 64 keys. Qs/Ks stored d-major, Vs row-major, Ps k-major.
// Dynamic smem: 4 * 64 * 68 floats = 69632 B.
// ---------------------------------------------------------------------------
#define QT 64
#define KT 64
#define FPAD 68

__global__ __launch_bounds__(256) void flash_attn2(float* __restrict__ out)
{
    extern __shared__ float sm[];
    float* Qs = sm;                    // [HS][FPAD]  Qs[d][q]
    float* Ks = Qs + HS * FPAD;        // [HS][FPAD]  Ks[d][k]
    float* Vs = Ks + HS * FPAD;        // [KT][FPAD]  Vs[j][d]
    float* Ps = Vs + KT * FPAD;        // [KT][FPAD]  Ps[j][q]

    const int bh = blockIdx.y;                    // b*NH + h
    const int qi = (gridDim.x - 1) - blockIdx.x;  // heavy q-tiles first
    const int q0 = qi * QT;
    const int tid = threadIdx.x;
    const int tx = tid & 15;
    const int ty = tid >> 4;

    const float* __restrict__ qp = g_q + (size_t)bh * T_SEQ * HS;
    const float* __restrict__ kp = g_k + (size_t)bh * T_SEQ * HS;
    const float* __restrict__ vp = g_v + (size_t)bh * T_SEQ * HS;

    // Loader mapping (shared by Q and K transposed loads):
    // row = tid&63, dchunk = tid>>6 ; 4 float4 loads, scatter to [d][row].
    const int lrow = tid & 63;
    const int ldc  = (tid >> 6) * 16;

    // Load Q tile transposed into Qs[d][q]
    {
        const float* qrow = qp + (size_t)(q0 + lrow) * HS + ldc;
#pragma unroll
        for (int i = 0; i < 4; i++) {
            float4 v = *(const float4*)(qrow + 4 * i);
            const int d = ldc + 4 * i;
            Qs[(d + 0) * FPAD + lrow] = v.x;
            Qs[(d + 1) * FPAD + lrow] = v.y;
            Qs[(d + 2) * FPAD + lrow] = v.z;
            Qs[(d + 3) * FPAD + lrow] = v.w;
        }
    }

    float o[4][4];
    float m[4], l[4];
#pragma unroll
    for (int i = 0; i < 4; i++) {
        m[i] = -INFINITY; l[i] = 0.f;
#pragma unroll
        for (int c = 0; c < 4; c++) o[i][c] = 0.f;
    }

    const int qrow0 = q0 + 4 * ty;     // this thread's first global query row

    for (int kt = 0; kt <= qi; kt++) {
        const int k0 = kt * KT;
        const bool diag = (kt == qi);

        __syncthreads();   // previous iteration's PV reads done

        // Load K transposed -> Ks[d][k]; V direct -> Vs[j][d]
        {
            const float* krow = kp + (size_t)(k0 + lrow) * HS + ldc;
#pragma unroll
            for (int i = 0; i < 4; i++) {
                float4 v = *(const float4*)(krow + 4 * i);
                const int d = ldc + 4 * i;
                Ks[(d + 0) * FPAD + lrow] = v.x;
                Ks[(d + 1) * FPAD + lrow] = v.y;
                Ks[(d + 2) * FPAD + lrow] = v.z;
                Ks[(d + 3) * FPAD + lrow] = v.w;
            }
#pragma unroll
            for (int i = 0; i < 4; i++) {
                const int f = tid + 256 * i;          // float4 index 0..1023
                const int j = f >> 4;
                const int d = (f & 15) * 4;
                *(float4*)&Vs[j * FPAD + d] =
                    *(const float4*)(vp + (size_t)(k0 + j) * HS + d);
            }
        }
        __syncthreads();

        // ---- S = Q K^T  (4x4 micro-tile) ----
        float s[4][4];
#pragma unroll
        for (int i = 0; i < 4; i++)
#pragma unroll
            for (int c = 0; c < 4; c++) s[i][c] = 0.f;

#pragma unroll 8
        for (int d = 0; d < HS; d++) {
            float4 qv = *(const float4*)&Qs[d * FPAD + 4 * ty];  // broadcast
            float4 kv = *(const float4*)&Ks[d * FPAD + 4 * tx];  // conflict-free
            float qa[4] = {qv.x, qv.y, qv.z, qv.w};
            float kb[4] = {kv.x, kv.y, kv.z, kv.w};
#pragma unroll
            for (int i = 0; i < 4; i++)
#pragma unroll
                for (int c = 0; c < 4; c++)
                    s[i][c] += qa[i] * kb[c];
        }

        // ---- online softmax per query row ----
#pragma unroll
        for (int i = 0; i < 4; i++) {
#pragma unroll
            for (int c = 0; c < 4; c++) s[i][c] *= 0.03125f;   // 1024^-0.5
            if (diag) {
                const int qg = qrow0 + i;
#pragma unroll
                for (int c = 0; c < 4; c++)
                    if (k0 + 4 * tx + c > qg) s[i][c] = -INFINITY;
            }
            float mt = fmaxf(fmaxf(s[i][0], s[i][1]), fmaxf(s[i][2], s[i][3]));
#pragma unroll
            for (int off = 8; off; off >>= 1)
                mt = fmaxf(mt, __shfl_xor_sync(0xffffffffu, mt, off));
            const float mnew = fmaxf(m[i], mt);
            const float alpha = __expf(m[i] - mnew);
            float rs = 0.f;
#pragma unroll
            for (int c = 0; c < 4; c++) {
                s[i][c] = __expf(s[i][c] - mnew);   // 0 for masked
                rs += s[i][c];
            }
#pragma unroll
            for (int off = 8; off; off >>= 1)
                rs += __shfl_xor_sync(0xffffffffu, rs, off);
            l[i] = l[i] * alpha + rs;
            m[i] = mnew;
#pragma unroll
            for (int c = 0; c < 4; c++) o[i][c] *= alpha;
        }

        // ---- store P transposed: Ps[k][q] ----
#pragma unroll
        for (int c = 0; c < 4; c++)
#pragma unroll
            for (int i = 0; i < 4; i++)
                Ps[(4 * tx + c) * FPAD + 4 * ty + i] = s[i][c];

        __syncthreads();

        // ---- O += P V  (4x4 micro-tile) ----
#pragma unroll 8
        for (int j = 0; j < KT; j++) {
            float4 pv = *(const float4*)&Ps[j * FPAD + 4 * ty];  // broadcast
            float4 vv = *(const float4*)&Vs[j * FPAD + 4 * tx];  // conflict-free
            float pa[4] = {pv.x, pv.y, pv.z, pv.w};
            float vb[4] = {vv.x, vv.y, vv.z, vv.w};
#pragma unroll
            for (int i = 0; i < 4; i++)
#pragma unroll
                for (int c = 0; c < 4; c++)
                    o[i][c] += pa[i] * vb[c];
        }
    }

    // ---- epilogue: O /= l, write [B,T,C] ----
    const int b = bh >> 4;
    const int h = bh & 15;
#pragma unroll
    for (int i = 0; i < 4; i++) {
        const float inv = 1.f / l[i];
        const size_t base = ((size_t)(b * T_SEQ + qrow0 + i)) * CDIM + h * HS + 4 * tx;
        float4 ov = make_float4(o[i][0] * inv, o[i][1] * inv,
                                o[i][2] * inv, o[i][3] * inv);
        *(float4*)((float*)out + base) = ov;
    }
}

// ---------------------------------------------------------------------------
extern "C" void kernel_launch(void* const* d_in, const int* in_sizes, int n_in,
                              void* d_out, int out_size)
{
    const float* x  = (const float*)d_in[0];
    const float* Wq = (const float*)d_in[1];
    const float* Wk = (const float*)d_in[2];
    const float* Wv = (const float*)d_in[3];
    float* out = (float*)d_out;

    dim3 ggrid(CDIM / BN, (BATCH * T_SEQ) / BM, 3);
    qkv_gemm_rope<<<ggrid, 256>>>(x, Wq, Wk, Wv);

    const int smem = 4 * HS * FPAD * (int)sizeof(float);   // 69632 B
    cudaFuncSetAttribute(flash_attn2,
                         cudaFuncAttributeMaxDynamicSharedMemorySize, smem);
    dim3 fgrid(T_SEQ / QT, BATCH * NH);
    flash_attn2<<<fgrid, 256, smem>>>(out);
}

// round 6
// speedup vs baseline: 2.6642x; 1.4613x over previous
#include <cuda_runtime.h>
#include <math.h>
#include <stdint.h>

// Problem constants
#define BATCH 2
#define T_SEQ 2048
#define CDIM  1024
#define NH    16
#define HS    64
#define QKV_ELEMS (BATCH * NH * T_SEQ * HS)   // 4 M floats = 16 MB each

// -2/1024 * ln(10000)
#define ROPE_COEF (-0.017988211f)

// Scratch (device globals — no allocation allowed in kernel_launch)
__device__ float g_q[QKV_ELEMS];
__device__ float g_k[QKV_ELEMS];
__device__ float g_v[QKV_ELEMS];

// ---------------------------------------------------------------------------
// Kernel A: out = x @ W^T via tf32 tensor-core mma, fused RoPE epilogue,
// writes [B, H, T, HS].  Block tile 128x64, 8 warps of 32x32, BK=16,
// double-buffered smem (pitch 20 -> conflict-free fragment LDS).
// Grid: (16, 32, 3), Block: 256
// ---------------------------------------------------------------------------
#define GBM 128
#define GBN 64
#define GBK 16
#define APITCH 20

__device__ __forceinline__ uint32_t f2tf32(float f) {
    uint32_t r;
    asm("cvt.rna.tf32.f32 %0, %1;" : "=r"(r) : "f"(f));
    return r;
}

__global__ __launch_bounds__(256) void qkv_gemm_tf32(
    const float* __restrict__ x,
    const float* __restrict__ Wq,
    const float* __restrict__ Wk,
    const float* __restrict__ Wv)
{
    __shared__ float As[2][GBM * APITCH];   // 2*128*20*4 = 20480 B
    __shared__ float Bs[2][GBN * APITCH];   // 2* 64*20*4 = 10240 B

    const int z = blockIdx.z;
    const float* __restrict__ W = (z == 0) ? Wq : ((z == 1) ? Wk : Wv);
    float* __restrict__ out = (z == 0) ? g_q : ((z == 1) ? g_k : g_v);

    const int m0 = blockIdx.y * GBM;
    const int h  = blockIdx.x;            // one head per block (GBN == HS)
    const int n0 = h * GBN;

    const int tid  = threadIdx.x;
    const int warp = tid >> 5;
    const int lane = tid & 31;
    const int g    = lane >> 2;           // groupID (0..7)
    const int tg   = lane & 3;            // thread-in-group

    const int wm = warp >> 1;             // 0..3  (32-row warp tile)
    const int wn = warp & 1;              // 0..1  (32-col warp tile)

    // Loader mapping
    const int row_a = tid >> 1;           // 0..127
    const int ka    = (tid & 1) * 8;      // 0 or 8
    const int row_b = tid >> 2;           // 0..63
    const int kb    = (tid & 3) * 4;      // 0,4,8,12

    const float* xbase = x + (size_t)(m0 + row_a) * CDIM + ka;
    const float* wbase = W + (size_t)(n0 + row_b) * CDIM + kb;

    float4 ra0, ra1, rb;

    auto ldg_stage = [&](int s) {
        const float* xp = xbase + s * GBK;
        ra0 = *(const float4*)(xp);
        ra1 = *(const float4*)(xp + 4);
        rb  = *(const float4*)(wbase + s * GBK);
    };
    auto sts_stage = [&](int buf) {
        float* A = As[buf] + row_a * APITCH + ka;
        A[0] = __uint_as_float(f2tf32(ra0.x));
        A[1] = __uint_as_float(f2tf32(ra0.y));
        A[2] = __uint_as_float(f2tf32(ra0.z));
        A[3] = __uint_as_float(f2tf32(ra0.w));
        A[4] = __uint_as_float(f2tf32(ra1.x));
        A[5] = __uint_as_float(f2tf32(ra1.y));
        A[6] = __uint_as_float(f2tf32(ra1.z));
        A[7] = __uint_as_float(f2tf32(ra1.w));
        float* B = Bs[buf] + row_b * APITCH + kb;
        B[0] = __uint_as_float(f2tf32(rb.x));
        B[1] = __uint_as_float(f2tf32(rb.y));
        B[2] = __uint_as_float(f2tf32(rb.z));
        B[3] = __uint_as_float(f2tf32(rb.w));
    };

    float c[2][4][4];
#pragma unroll
    for (int mi = 0; mi < 2; mi++)
#pragma unroll
        for (int ni = 0; ni < 4; ni++)
#pragma unroll
            for (int r = 0; r < 4; r++) c[mi][ni][r] = 0.f;

    auto compute_stage = [&](int buf) {
        const float* A = As[buf];
        const float* B = Bs[buf];
#pragma unroll
        for (int k8 = 0; k8 < GBK; k8 += 8) {
            uint32_t a[2][4];
#pragma unroll
            for (int mi = 0; mi < 2; mi++) {
                const int base = (wm * 32 + mi * 16 + g) * APITCH + k8 + tg;
                a[mi][0] = __float_as_uint(A[base]);
                a[mi][1] = __float_as_uint(A[base + 8 * APITCH]);
                a[mi][2] = __float_as_uint(A[base + 4]);
                a[mi][3] = __float_as_uint(A[base + 8 * APITCH + 4]);
            }
            uint32_t bf[4][2];
#pragma unroll
            for (int ni = 0; ni < 4; ni++) {
                const int base = (wn * 32 + ni * 8 + g) * APITCH + k8 + tg;
                bf[ni][0] = __float_as_uint(B[base]);
                bf[ni][1] = __float_as_uint(B[base + 4]);
            }
#pragma unroll
            for (int mi = 0; mi < 2; mi++)
#pragma unroll
                for (int ni = 0; ni < 4; ni++) {
                    asm volatile(
                        "mma.sync.aligned.m16n8k8.row.col.f32.tf32.tf32.f32 "
                        "{%0,%1,%2,%3}, {%4,%5,%6,%7}, {%8,%9}, {%0,%1,%2,%3};"
                        : "+f"(c[mi][ni][0]), "+f"(c[mi][ni][1]),
                          "+f"(c[mi][ni][2]), "+f"(c[mi][ni][3])
                        : "r"(a[mi][0]), "r"(a[mi][1]), "r"(a[mi][2]), "r"(a[mi][3]),
                          "r"(bf[ni][0]), "r"(bf[ni][1]));
                }
        }
    };

    const int stages = CDIM / GBK;   // 64
    ldg_stage(0);
    sts_stage(0);
    ldg_stage(1);
    __syncthreads();

    for (int s = 0; s < stages; s++) {
        compute_stage(s & 1);
        if (s + 1 < stages) {
            __syncthreads();
            sts_stage((s + 1) & 1);
            if (s + 2 < stages) ldg_stage(s + 2);
            __syncthreads();
        }
    }

    // ---- epilogue: RoPE (z<2) + store [B,H,T,HS] ----
#pragma unroll
    for (int mi = 0; mi < 2; mi++) {
#pragma unroll
        for (int ni = 0; ni < 4; ni++) {
            const int d = wn * 32 + ni * 8 + 2 * tg;   // local head dim (even)
            float theta = 0.f;
            if (z < 2) theta = expf((float)(d >> 1) * ROPE_COEF);
#pragma unroll
            for (int half = 0; half < 2; half++) {
                const int m = m0 + wm * 32 + mi * 16 + g + half * 8;
                const int t = m & (T_SEQ - 1);
                const int b = m >> 11;
                const float v0 = c[mi][ni][half * 2 + 0];
                const float v1 = c[mi][ni][half * 2 + 1];
                const size_t base =
                    (((size_t)(b * NH + h) * T_SEQ) + t) * HS + d;
                if (z < 2) {
                    // fp32 Cody-Waite mod 2pi: n*6.28125 exact (7+9<=24 bits)
                    const float ang = (float)t * theta;
                    const float nq = floorf(ang * 0.15915494309f);
                    float r = fmaf(-nq, 6.28125f, ang);
                    r = fmaf(-nq, 1.9353072e-3f, r);
                    const float sn = __sinf(r);
                    const float cs = __cosf(r);
                    float2 o = make_float2(v0 * cs - v1 * sn,
                                           v1 * cs + v0 * sn);
                    *(float2*)(out + base) = o;
                } else {
                    *(float2*)(out + base) = make_float2(v0, v1);
                }
            }
        }
    }
}

// ---------------------------------------------------------------------------
// Kernel B: register-tiled causal flash attention (unchanged from R3).
// ---------------------------------------------------------------------------
#define QT 64
#define KT 64
#define FPAD 68

__global__ __launch_bounds__(256) void flash_attn2(float* __restrict__ out)
{
    extern __shared__ float sm[];
    float* Qs = sm;                    // [HS][FPAD]  Qs[d][q]
    float* Ks = Qs + HS * FPAD;        // [HS][FPAD]  Ks[d][k]
    float* Vs = Ks + HS * FPAD;        // [KT][FPAD]  Vs[j][d]
    float* Ps = Vs + KT * FPAD;        // [KT][FPAD]  Ps[j][q]

    const int bh = blockIdx.y;
    const int qi = (gridDim.x - 1) - blockIdx.x;  // heavy q-tiles first
    const int q0 = qi * QT;
    const int tid = threadIdx.x;
    const int tx = tid & 15;
    const int ty = tid >> 4;

    const float* __restrict__ qp = g_q + (size_t)bh * T_SEQ * HS;
    const float* __restrict__ kp = g_k + (size_t)bh * T_SEQ * HS;
    const float* __restrict__ vp = g_v + (size_t)bh * T_SEQ * HS;

    const int lrow = tid & 63;
    const int ldc  = (tid >> 6) * 16;

    {
        const float* qrow = qp + (size_t)(q0 + lrow) * HS + ldc;
#pragma unroll
        for (int i = 0; i < 4; i++) {
            float4 v = *(const float4*)(qrow + 4 * i);
            const int d = ldc + 4 * i;
            Qs[(d + 0) * FPAD + lrow] = v.x;
            Qs[(d + 1) * FPAD + lrow] = v.y;
            Qs[(d + 2) * FPAD + lrow] = v.z;
            Qs[(d + 3) * FPAD + lrow] = v.w;
        }
    }

    float o[4][4];
    float m[4], l[4];
#pragma unroll
    for (int i = 0; i < 4; i++) {
        m[i] = -INFINITY; l[i] = 0.f;
#pragma unroll
        for (int c = 0; c < 4; c++) o[i][c] = 0.f;
    }

    const int qrow0 = q0 + 4 * ty;

    for (int kt = 0; kt <= qi; kt++) {
        const int k0 = kt * KT;
        const bool diag = (kt == qi);

        __syncthreads();

        {
            const float* krow = kp + (size_t)(k0 + lrow) * HS + ldc;
#pragma unroll
            for (int i = 0; i < 4; i++) {
                float4 v = *(const float4*)(krow + 4 * i);
                const int d = ldc + 4 * i;
                Ks[(d + 0) * FPAD + lrow] = v.x;
                Ks[(d + 1) * FPAD + lrow] = v.y;
                Ks[(d + 2) * FPAD + lrow] = v.z;
                Ks[(d + 3) * FPAD + lrow] = v.w;
            }
#pragma unroll
            for (int i = 0; i < 4; i++) {
                const int f = tid + 256 * i;
                const int j = f >> 4;
                const int d = (f & 15) * 4;
                *(float4*)&Vs[j * FPAD + d] =
                    *(const float4*)(vp + (size_t)(k0 + j) * HS + d);
            }
        }
        __syncthreads();

        float s[4][4];
#pragma unroll
        for (int i = 0; i < 4; i++)
#pragma unroll
            for (int c = 0; c < 4; c++) s[i][c] = 0.f;

#pragma unroll 8
        for (int d = 0; d < HS; d++) {
            float4 qv = *(const float4*)&Qs[d * FPAD + 4 * ty];
            float4 kv = *(const float4*)&Ks[d * FPAD + 4 * tx];
            float qa[4] = {qv.x, qv.y, qv.z, qv.w};
            float kb[4] = {kv.x, kv.y, kv.z, kv.w};
#pragma unroll
            for (int i = 0; i < 4; i++)
#pragma unroll
                for (int c = 0; c < 4; c++)
                    s[i][c] += qa[i] * kb[c];
        }

#pragma unroll
        for (int i = 0; i < 4; i++) {
#pragma unroll
            for (int c = 0; c < 4; c++) s[i][c] *= 0.03125f;
            if (diag) {
                const int qg = qrow0 + i;
#pragma unroll
                for (int c = 0; c < 4; c++)
                    if (k0 + 4 * tx + c > qg) s[i][c] = -INFINITY;
            }
            float mt = fmaxf(fmaxf(s[i][0], s[i][1]), fmaxf(s[i][2], s[i][3]));
#pragma unroll
            for (int off = 8; off; off >>= 1)
                mt = fmaxf(mt, __shfl_xor_sync(0xffffffffu, mt, off));
            const float mnew = fmaxf(m[i], mt);
            const float alpha = __expf(m[i] - mnew);
            float rs = 0.f;
#pragma unroll
            for (int c = 0; c < 4; c++) {
                s[i][c] = __expf(s[i][c] - mnew);
                rs += s[i][c];
            }
#pragma unroll
            for (int off = 8; off; off >>= 1)
                rs += __shfl_xor_sync(0xffffffffu, rs, off);
            l[i] = l[i] * alpha + rs;
            m[i] = mnew;
#pragma unroll
            for (int c = 0; c < 4; c++) o[i][c] *= alpha;
        }

#pragma unroll
        for (int c = 0; c < 4; c++)
#pragma unroll
            for (int i = 0; i < 4; i++)
                Ps[(4 * tx + c) * FPAD + 4 * ty + i] = s[i][c];

        __syncthreads();

#pragma unroll 8
        for (int j = 0; j < KT; j++) {
            float4 pv = *(const float4*)&Ps[j * FPAD + 4 * ty];
            float4 vv = *(const float4*)&Vs[j * FPAD + 4 * tx];
            float pa[4] = {pv.x, pv.y, pv.z, pv.w};
            float vb[4] = {vv.x, vv.y, vv.z, vv.w};
#pragma unroll
            for (int i = 0; i < 4; i++)
#pragma unroll
                for (int c = 0; c < 4; c++)
                    o[i][c] += pa[i] * vb[c];
        }
    }

    const int b = bh >> 4;
    const int h = bh & 15;
#pragma unroll
    for (int i = 0; i < 4; i++) {
        const float inv = 1.f / l[i];
        const size_t base = ((size_t)(b * T_SEQ + qrow0 + i)) * CDIM + h * HS + 4 * tx;
        float4 ov = make_float4(o[i][0] * inv, o[i][1] * inv,
                                o[i][2] * inv, o[i][3] * inv);
        *(float4*)((float*)out + base) = ov;
    }
}

// ---------------------------------------------------------------------------
extern "C" void kernel_launch(void* const* d_in, const int* in_sizes, int n_in,
                              void* d_out, int out_size)
{
    const float* x  = (const float*)d_in[0];
    const float* Wq = (const float*)d_in[1];
    const float* Wk = (const float*)d_in[2];
    const float* Wv = (const float*)d_in[3];
    float* out = (float*)d_out;

    dim3 ggrid(CDIM / GBN, (BATCH * T_SEQ) / GBM, 3);
    qkv_gemm_tf32<<<ggrid, 256>>>(x, Wq, Wk, Wv);

    const int smem = 4 * HS * FPAD * (int)sizeof(float);   // 69632 B
    cudaFuncSetAttribute(flash_attn2,
                         cudaFuncAttributeMaxDynamicSharedMemorySize, smem);
    dim3 fgrid(T_SEQ / QT, BATCH * NH);
    flash_attn2<<<fgrid, 256, smem>>>(out);
}

// round 7
// speedup vs baseline: 4.4724x; 1.6787x over previous
#include <cuda_runtime.h>
#include <math.h>
#include <stdint.h>

// Problem constants
#define BATCH 2
#define T_SEQ 2048
#define CDIM  1024
#define NH    16
#define HS    64
#define QKV_ELEMS (BATCH * NH * T_SEQ * HS)   // 4 M floats = 16 MB each

// -2/1024 * ln(10000)
#define ROPE_COEF (-0.017988211f)

// Scratch (device globals — no allocation allowed in kernel_launch)
__device__ float g_q[QKV_ELEMS];
__device__ float g_k[QKV_ELEMS];
__device__ float g_v[QKV_ELEMS];

__device__ __forceinline__ uint32_t f2tf32(float f) {
    uint32_t r;
    asm("cvt.rna.tf32.f32 %0, %1;" : "=r"(r) : "f"(f));
    return r;
}

#define MMA_TF32(C, A0, A1, A2, A3, B0, B1)                                    \
    asm volatile(                                                              \
        "mma.sync.aligned.m16n8k8.row.col.f32.tf32.tf32.f32 "                  \
        "{%0,%1,%2,%3}, {%4,%5,%6,%7}, {%8,%9}, {%0,%1,%2,%3};"                \
        : "+f"((C)[0]), "+f"((C)[1]), "+f"((C)[2]), "+f"((C)[3])               \
        : "r"(A0), "r"(A1), "r"(A2), "r"(A3), "r"(B0), "r"(B1))

// ---------------------------------------------------------------------------
// Kernel A: out = x @ W^T via tf32 mma, fused RoPE epilogue, [B,H,T,HS].
// (unchanged from R5)
// ---------------------------------------------------------------------------
#define GBM 128
#define GBN 64
#define GBK 16
#define APITCH 20

__global__ __launch_bounds__(256) void qkv_gemm_tf32(
    const float* __restrict__ x,
    const float* __restrict__ Wq,
    const float* __restrict__ Wk,
    const float* __restrict__ Wv)
{
    __shared__ float As[2][GBM * APITCH];
    __shared__ float Bs[2][GBN * APITCH];

    const int z = blockIdx.z;
    const float* __restrict__ W = (z == 0) ? Wq : ((z == 1) ? Wk : Wv);
    float* __restrict__ out = (z == 0) ? g_q : ((z == 1) ? g_k : g_v);

    const int m0 = blockIdx.y * GBM;
    const int h  = blockIdx.x;
    const int n0 = h * GBN;

    const int tid  = threadIdx.x;
    const int warp = tid >> 5;
    const int lane = tid & 31;
    const int g    = lane >> 2;
    const int tg   = lane & 3;

    const int wm = warp >> 1;
    const int wn = warp & 1;

    const int row_a = tid >> 1;
    const int ka    = (tid & 1) * 8;
    const int row_b = tid >> 2;
    const int kb    = (tid & 3) * 4;

    const float* xbase = x + (size_t)(m0 + row_a) * CDIM + ka;
    const float* wbase = W + (size_t)(n0 + row_b) * CDIM + kb;

    float4 ra0, ra1, rb;

    auto ldg_stage = [&](int s) {
        const float* xp = xbase + s * GBK;
        ra0 = *(const float4*)(xp);
        ra1 = *(const float4*)(xp + 4);
        rb  = *(const float4*)(wbase + s * GBK);
    };
    auto sts_stage = [&](int buf) {
        float* A = As[buf] + row_a * APITCH + ka;
        A[0] = __uint_as_float(f2tf32(ra0.x));
        A[1] = __uint_as_float(f2tf32(ra0.y));
        A[2] = __uint_as_float(f2tf32(ra0.z));
        A[3] = __uint_as_float(f2tf32(ra0.w));
        A[4] = __uint_as_float(f2tf32(ra1.x));
        A[5] = __uint_as_float(f2tf32(ra1.y));
        A[6] = __uint_as_float(f2tf32(ra1.z));
        A[7] = __uint_as_float(f2tf32(ra1.w));
        float* B = Bs[buf] + row_b * APITCH + kb;
        B[0] = __uint_as_float(f2tf32(rb.x));
        B[1] = __uint_as_float(f2tf32(rb.y));
        B[2] = __uint_as_float(f2tf32(rb.z));
        B[3] = __uint_as_float(f2tf32(rb.w));
    };

    float c[2][4][4];
#pragma unroll
    for (int mi = 0; mi < 2; mi++)
#pragma unroll
        for (int ni = 0; ni < 4; ni++)
#pragma unroll
            for (int r = 0; r < 4; r++) c[mi][ni][r] = 0.f;

    auto compute_stage = [&](int buf) {
        const float* A = As[buf];
        const float* B = Bs[buf];
#pragma unroll
        for (int k8 = 0; k8 < GBK; k8 += 8) {
            uint32_t a[2][4];
#pragma unroll
            for (int mi = 0; mi < 2; mi++) {
                const int base = (wm * 32 + mi * 16 + g) * APITCH + k8 + tg;
                a[mi][0] = __float_as_uint(A[base]);
                a[mi][1] = __float_as_uint(A[base + 8 * APITCH]);
                a[mi][2] = __float_as_uint(A[base + 4]);
                a[mi][3] = __float_as_uint(A[base + 8 * APITCH + 4]);
            }
            uint32_t bf[4][2];
#pragma unroll
            for (int ni = 0; ni < 4; ni++) {
                const int base = (wn * 32 + ni * 8 + g) * APITCH + k8 + tg;
                bf[ni][0] = __float_as_uint(B[base]);
                bf[ni][1] = __float_as_uint(B[base + 4]);
            }
#pragma unroll
            for (int mi = 0; mi < 2; mi++)
#pragma unroll
                for (int ni = 0; ni < 4; ni++)
                    MMA_TF32(c[mi][ni], a[mi][0], a[mi][1], a[mi][2], a[mi][3],
                             bf[ni][0], bf[ni][1]);
        }
    };

    const int stages = CDIM / GBK;
    ldg_stage(0);
    sts_stage(0);
    ldg_stage(1);
    __syncthreads();

    for (int s = 0; s < stages; s++) {
        compute_stage(s & 1);
        if (s + 1 < stages) {
            __syncthreads();
            sts_stage((s + 1) & 1);
            if (s + 2 < stages) ldg_stage(s + 2);
            __syncthreads();
        }
    }

#pragma unroll
    for (int mi = 0; mi < 2; mi++) {
#pragma unroll
        for (int ni = 0; ni < 4; ni++) {
            const int d = wn * 32 + ni * 8 + 2 * tg;
            float theta = 0.f;
            if (z < 2) theta = expf((float)(d >> 1) * ROPE_COEF);
#pragma unroll
            for (int half = 0; half < 2; half++) {
                const int m = m0 + wm * 32 + mi * 16 + g + half * 8;
                const int t = m & (T_SEQ - 1);
                const int b = m >> 11;
                const float v0 = c[mi][ni][half * 2 + 0];
                const float v1 = c[mi][ni][half * 2 + 1];
                const size_t base =
                    (((size_t)(b * NH + h) * T_SEQ) + t) * HS + d;
                if (z < 2) {
                    const float ang = (float)t * theta;
                    const float nq = floorf(ang * 0.15915494309f);
                    float r = fmaf(-nq, 6.28125f, ang);
                    r = fmaf(-nq, 1.9353072e-3f, r);
                    const float sn = __sinf(r);
                    const float cs = __cosf(r);
                    *(float2*)(out + base) =
                        make_float2(v0 * cs - v1 * sn, v1 * cs + v0 * sn);
                } else {
                    *(float2*)(out + base) = make_float2(v0, v1);
                }
            }
        }
    }
}

// ---------------------------------------------------------------------------
// Kernel B: tf32 mma flash attention.
// Block = 64 queries x 64-key tiles; 128 threads, 4 warps; each warp owns
// 16 full S rows (16 x 64). Smem pitch 68 (conflict-free fragment LDS).
// ---------------------------------------------------------------------------
#define FPAD 68

__global__ __launch_bounds__(128) void flash_attn3(float* __restrict__ out)
{
    extern __shared__ float sm[];
    float* Qs = sm;               // [64][FPAD]  Qs[q][d]    (tf32)
    float* Ks = Qs + 64 * FPAD;   // [64][FPAD]  Ks[key][d]  (tf32)
    float* Vt = Ks + 64 * FPAD;   // [64][FPAD]  Vt[d][j]    (tf32, transposed)
    float* Ps = Vt + 64 * FPAD;   // [64][FPAD]  Ps[q][j]    (tf32)

    const int bh = blockIdx.y;                    // b*NH + h
    const int qi = (gridDim.x - 1) - blockIdx.x;  // heavy q-tiles first
    const int q0 = qi * 64;
    const int tid  = threadIdx.x;
    const int warp = tid >> 5;
    const int lane = tid & 31;
    const int g  = lane >> 2;
    const int tg = lane & 3;
    const int r0 = warp * 16 + g;                 // local S/O row (also +8)

    const float* __restrict__ qp = g_q + (size_t)bh * T_SEQ * HS;
    const float* __restrict__ kp = g_k + (size_t)bh * T_SEQ * HS;
    const float* __restrict__ vp = g_v + (size_t)bh * T_SEQ * HS;

    // Load Q tile (row-major, cvt to tf32)
#pragma unroll
    for (int i = 0; i < 8; i++) {
        const int f = tid + 128 * i;
        const int j = f >> 4;
        const int d4 = (f & 15) * 4;
        float4 v = *(const float4*)(qp + (size_t)(q0 + j) * HS + d4);
        uint4 u = make_uint4(f2tf32(v.x), f2tf32(v.y), f2tf32(v.z), f2tf32(v.w));
        *(uint4*)&Qs[j * FPAD + d4] = u;
    }

    float m[2] = {-INFINITY, -INFINITY};
    float l[2] = {0.f, 0.f};
    float co[8][4];
#pragma unroll
    for (int ni = 0; ni < 8; ni++)
#pragma unroll
        for (int c = 0; c < 4; c++) co[ni][c] = 0.f;

    // V-transpose loader mapping: lane -> conflict-free scatter
    const int vj = tid & 63;
    const int vdb = (tid >> 6) * 32;

    for (int kt = 0; kt <= qi; kt++) {
        const int k0 = kt * 64;
        const bool diag = (kt == qi);

        __syncthreads();   // previous tile's Ks/Vt reads complete

        // K tile row-major (cvt tf32)
#pragma unroll
        for (int i = 0; i < 8; i++) {
            const int f = tid + 128 * i;
            const int j = f >> 4;
            const int d4 = (f & 15) * 4;
            float4 v = *(const float4*)(kp + (size_t)(k0 + j) * HS + d4);
            uint4 u = make_uint4(f2tf32(v.x), f2tf32(v.y), f2tf32(v.z), f2tf32(v.w));
            *(uint4*)&Ks[j * FPAD + d4] = u;
        }
        // V tile transposed -> Vt[d][j] (cvt tf32)
#pragma unroll
        for (int i = 0; i < 8; i++) {
            const int d = vdb + 4 * i;
            float4 v = *(const float4*)(vp + (size_t)(k0 + vj) * HS + d);
            Vt[(d + 0) * FPAD + vj] = __uint_as_float(f2tf32(v.x));
            Vt[(d + 1) * FPAD + vj] = __uint_as_float(f2tf32(v.y));
            Vt[(d + 2) * FPAD + vj] = __uint_as_float(f2tf32(v.z));
            Vt[(d + 3) * FPAD + vj] = __uint_as_float(f2tf32(v.w));
        }
        __syncthreads();

        // ---- S = Q K^T : warp computes rows [warp*16, +16) x all 64 cols ----
        float cs[8][4];
#pragma unroll
        for (int ni = 0; ni < 8; ni++)
#pragma unroll
            for (int c = 0; c < 4; c++) cs[ni][c] = 0.f;

#pragma unroll
        for (int k8 = 0; k8 < HS; k8 += 8) {
            const uint32_t a0 = __float_as_uint(Qs[r0 * FPAD + k8 + tg]);
            const uint32_t a1 = __float_as_uint(Qs[(r0 + 8) * FPAD + k8 + tg]);
            const uint32_t a2 = __float_as_uint(Qs[r0 * FPAD + k8 + tg + 4]);
            const uint32_t a3 = __float_as_uint(Qs[(r0 + 8) * FPAD + k8 + tg + 4]);
#pragma unroll
            for (int ni = 0; ni < 8; ni++) {
                const uint32_t b0 = __float_as_uint(Ks[(ni * 8 + g) * FPAD + k8 + tg]);
                const uint32_t b1 = __float_as_uint(Ks[(ni * 8 + g) * FPAD + k8 + tg + 4]);
                MMA_TF32(cs[ni], a0, a1, a2, a3, b0, b1);
            }
        }

        // ---- scale + causal mask + online softmax (rows r0, r0+8) ----
        float mt[2] = {-INFINITY, -INFINITY};
#pragma unroll
        for (int ni = 0; ni < 8; ni++) {
#pragma unroll
            for (int c = 0; c < 4; c++) {
                float v = cs[ni][c] * 0.03125f;
                if (diag) {
                    const int col = k0 + ni * 8 + 2 * tg + (c & 1);
                    const int row = q0 + r0 + 8 * (c >> 1);
                    if (col > row) v = -INFINITY;
                }
                cs[ni][c] = v;
                mt[c >> 1] = fmaxf(mt[c >> 1], v);
            }
        }
#pragma unroll
        for (int h2 = 0; h2 < 2; h2++) {
            mt[h2] = fmaxf(mt[h2], __shfl_xor_sync(0xffffffffu, mt[h2], 1));
            mt[h2] = fmaxf(mt[h2], __shfl_xor_sync(0xffffffffu, mt[h2], 2));
        }
        float alpha[2];
#pragma unroll
        for (int h2 = 0; h2 < 2; h2++) {
            const float mnew = fmaxf(m[h2], mt[h2]);
            alpha[h2] = __expf(m[h2] - mnew);
            m[h2] = mnew;
        }
        float rs[2] = {0.f, 0.f};
#pragma unroll
        for (int ni = 0; ni < 8; ni++) {
#pragma unroll
            for (int c = 0; c < 4; c++) {
                const float p = __expf(cs[ni][c] - m[c >> 1]);
                cs[ni][c] = p;
                rs[c >> 1] += p;
            }
        }
#pragma unroll
        for (int h2 = 0; h2 < 2; h2++) {
            rs[h2] += __shfl_xor_sync(0xffffffffu, rs[h2], 1);
            rs[h2] += __shfl_xor_sync(0xffffffffu, rs[h2], 2);
            l[h2] = l[h2] * alpha[h2] + rs[h2];
        }
#pragma unroll
        for (int ni = 0; ni < 8; ni++)
#pragma unroll
            for (int c = 0; c < 4; c++) co[ni][c] *= alpha[c >> 1];

        // ---- store P (tf32) to warp-private Ps rows ----
#pragma unroll
        for (int ni = 0; ni < 8; ni++) {
            float2 p0 = make_float2(__uint_as_float(f2tf32(cs[ni][0])),
                                    __uint_as_float(f2tf32(cs[ni][1])));
            float2 p1 = make_float2(__uint_as_float(f2tf32(cs[ni][2])),
                                    __uint_as_float(f2tf32(cs[ni][3])));
            *(float2*)&Ps[r0 * FPAD + ni * 8 + 2 * tg] = p0;
            *(float2*)&Ps[(r0 + 8) * FPAD + ni * 8 + 2 * tg] = p1;
        }
        __syncwarp();

        // ---- O += P V ----
#pragma unroll
        for (int j8 = 0; j8 < 64; j8 += 8) {
            const uint32_t a0 = __float_as_uint(Ps[r0 * FPAD + j8 + tg]);
            const uint32_t a1 = __float_as_uint(Ps[(r0 + 8) * FPAD + j8 + tg]);
            const uint32_t a2 = __float_as_uint(Ps[r0 * FPAD + j8 + tg + 4]);
            const uint32_t a3 = __float_as_uint(Ps[(r0 + 8) * FPAD + j8 + tg + 4]);
#pragma unroll
            for (int ni = 0; ni < 8; ni++) {
                const uint32_t b0 = __float_as_uint(Vt[(ni * 8 + g) * FPAD + j8 + tg]);
                const uint32_t b1 = __float_as_uint(Vt[(ni * 8 + g) * FPAD + j8 + tg + 4]);
                MMA_TF32(co[ni], a0, a1, a2, a3, b0, b1);
            }
        }
    }

    // ---- epilogue: O /= l, write [B,T,C] ----
    const int b = bh >> 4;
    const int h = bh & 15;
    const float inv0 = 1.f / l[0];
    const float inv1 = 1.f / l[1];
    const size_t base0 = ((size_t)(b * T_SEQ + q0 + r0)) * CDIM + h * HS;
    const size_t base1 = ((size_t)(b * T_SEQ + q0 + r0 + 8)) * CDIM + h * HS;
#pragma unroll
    for (int ni = 0; ni < 8; ni++) {
        const int d = ni * 8 + 2 * tg;
        *(float2*)(out + base0 + d) = make_float2(co[ni][0] * inv0, co[ni][1] * inv0);
        *(float2*)(out + base1 + d) = make_float2(co[ni][2] * inv1, co[ni][3] * inv1);
    }
}

// ---------------------------------------------------------------------------
extern "C" void kernel_launch(void* const* d_in, const int* in_sizes, int n_in,
                              void* d_out, int out_size)
{
    const float* x  = (const float*)d_in[0];
    const float* Wq = (const float*)d_in[1];
    const float* Wk = (const float*)d_in[2];
    const float* Wv = (const float*)d_in[3];
    float* out = (float*)d_out;

    dim3 ggrid(CDIM / GBN, (BATCH * T_SEQ) / GBM, 3);
    qkv_gemm_tf32<<<ggrid, 256>>>(x, Wq, Wk, Wv);

    const int smem = 4 * 64 * FPAD * (int)sizeof(float);   // 69632 B
    cudaFuncSetAttribute(flash_attn3,
                         cudaFuncAttributeMaxDynamicSharedMemorySize, smem);
    dim3 fgrid(T_SEQ / 64, BATCH * NH);
    flash_attn3<<<fgrid, 128, smem>>>(out);
}

// round 9
// speedup vs baseline: 4.8299x; 1.0799x over previous
#include <cuda_runtime.h>
#include <math.h>
#include <stdint.h>

// Problem constants
#define BATCH 2
#define T_SEQ 2048
#define CDIM  1024
#define NH    16
#define HS    64
#define QKV_ELEMS (BATCH * NH * T_SEQ * HS)   // 4 M floats = 16 MB each

// -2/1024 * ln(10000)
#define ROPE_COEF (-0.017988211f)

// Scratch (device globals — no allocation allowed in kernel_launch)
__device__ float g_q[QKV_ELEMS];
__device__ float g_k[QKV_ELEMS];
__device__ float g_v[QKV_ELEMS];

__device__ __forceinline__ uint32_t f2tf32(float f) {
    uint32_t r;
    asm("cvt.rna.tf32.f32 %0, %1;" : "=r"(r) : "f"(f));
    return r;
}
__device__ __forceinline__ float f2tf32f(float f) {
    return __uint_as_float(f2tf32(f));
}

#define MMA_TF32(C, A0, A1, A2, A3, B0, B1)                                    \
    asm volatile(                                                              \
        "mma.sync.aligned.m16n8k8.row.col.f32.tf32.tf32.f32 "                  \
        "{%0,%1,%2,%3}, {%4,%5,%6,%7}, {%8,%9}, {%0,%1,%2,%3};"                \
        : "+f"((C)[0]), "+f"((C)[1]), "+f"((C)[2]), "+f"((C)[3])               \
        : "r"(A0), "r"(A1), "r"(A2), "r"(A3), "r"(B0), "r"(B1))

// ---------------------------------------------------------------------------
// Kernel A: out = x @ W^T via tf32 mma, fused RoPE epilogue, [B,H,T,HS].
// Block tile 128x64, 8 warps of 32x32, BK=32, double-buffered dynamic smem.
// Grid: (16, 32, 3), Block: 256
// ---------------------------------------------------------------------------
#define GBM 128
#define GBN 64
#define GBK 32
#define APITCH 36

__global__ __launch_bounds__(256) void qkv_gemm_tf32(
    const float* __restrict__ x,
    const float* __restrict__ Wq,
    const float* __restrict__ Wk,
    const float* __restrict__ Wv)
{
    extern __shared__ float gsm[];
    float* As = gsm;                        // [2][GBM*APITCH]
    float* Bs = gsm + 2 * GBM * APITCH;     // [2][GBN*APITCH]

    const int z = blockIdx.z;
    const float* __restrict__ W = (z == 0) ? Wq : ((z == 1) ? Wk : Wv);
    float* __restrict__ out = (z == 0) ? g_q : ((z == 1) ? g_k : g_v);

    const int m0 = blockIdx.y * GBM;
    const int h  = blockIdx.x;
    const int n0 = h * GBN;

    const int tid  = threadIdx.x;
    const int warp = tid >> 5;
    const int lane = tid & 31;
    const int g    = lane >> 2;
    const int tg   = lane & 3;

    const int wm = warp >> 1;
    const int wn = warp & 1;

    // Loader mapping (BK=32)
    const int row_a = tid >> 1;           // 0..127
    const int ka    = (tid & 1) * 16;     // 0 or 16
    const int row_b = tid >> 2;           // 0..63
    const int kb    = (tid & 3) * 8;      // 0,8,16,24

    const float* xbase = x + (size_t)(m0 + row_a) * CDIM + ka;
    const float* wbase = W + (size_t)(n0 + row_b) * CDIM + kb;

    float4 ra[4], rb[2];

    auto ldg_stage = [&](int s) {
        const float* xp = xbase + s * GBK;
#pragma unroll
        for (int i = 0; i < 4; i++) ra[i] = *(const float4*)(xp + 4 * i);
        const float* wp = wbase + s * GBK;
#pragma unroll
        for (int i = 0; i < 2; i++) rb[i] = *(const float4*)(wp + 4 * i);
    };
    auto sts_stage = [&](int buf) {
        float* A = As + buf * GBM * APITCH + row_a * APITCH + ka;
#pragma unroll
        for (int i = 0; i < 4; i++) {
            float4 t = make_float4(f2tf32f(ra[i].x), f2tf32f(ra[i].y),
                                   f2tf32f(ra[i].z), f2tf32f(ra[i].w));
            *(float4*)(A + 4 * i) = t;
        }
        float* B = Bs + buf * GBN * APITCH + row_b * APITCH + kb;
#pragma unroll
        for (int i = 0; i < 2; i++) {
            float4 t = make_float4(f2tf32f(rb[i].x), f2tf32f(rb[i].y),
                                   f2tf32f(rb[i].z), f2tf32f(rb[i].w));
            *(float4*)(B + 4 * i) = t;
        }
    };

    float c[2][4][4];
#pragma unroll
    for (int mi = 0; mi < 2; mi++)
#pragma unroll
        for (int ni = 0; ni < 4; ni++)
#pragma unroll
            for (int r = 0; r < 4; r++) c[mi][ni][r] = 0.f;

    auto compute_stage = [&](int buf) {
        const float* A = As + buf * GBM * APITCH;
        const float* B = Bs + buf * GBN * APITCH;
#pragma unroll
        for (int k8 = 0; k8 < GBK; k8 += 8) {
            uint32_t a[2][4];
#pragma unroll
            for (int mi = 0; mi < 2; mi++) {
                const int base = (wm * 32 + mi * 16 + g) * APITCH + k8 + tg;
                a[mi][0] = __float_as_uint(A[base]);
                a[mi][1] = __float_as_uint(A[base + 8 * APITCH]);
                a[mi][2] = __float_as_uint(A[base + 4]);
                a[mi][3] = __float_as_uint(A[base + 8 * APITCH + 4]);
            }
            uint32_t bf[4][2];
#pragma unroll
            for (int ni = 0; ni < 4; ni++) {
                const int base = (wn * 32 + ni * 8 + g) * APITCH + k8 + tg;
                bf[ni][0] = __float_as_uint(B[base]);
                bf[ni][1] = __float_as_uint(B[base + 4]);
            }
#pragma unroll
            for (int mi = 0; mi < 2; mi++)
#pragma unroll
                for (int ni = 0; ni < 4; ni++)
                    MMA_TF32(c[mi][ni], a[mi][0], a[mi][1], a[mi][2], a[mi][3],
                             bf[ni][0], bf[ni][1]);
        }
    };

    const int stages = CDIM / GBK;   // 32
    ldg_stage(0);
    sts_stage(0);
    ldg_stage(1);
    __syncthreads();

    for (int s = 0; s < stages; s++) {
        compute_stage(s & 1);
        if (s + 1 < stages) {
            __syncthreads();
            sts_stage((s + 1) & 1);
            if (s + 2 < stages) ldg_stage(s + 2);
            __syncthreads();
        }
    }

    // ---- epilogue: RoPE (z<2) + store [B,H,T,HS] ----
#pragma unroll
    for (int mi = 0; mi < 2; mi++) {
#pragma unroll
        for (int ni = 0; ni < 4; ni++) {
            const int d = wn * 32 + ni * 8 + 2 * tg;
            float theta = 0.f;
            if (z < 2) theta = expf((float)(d >> 1) * ROPE_COEF);
#pragma unroll
            for (int half = 0; half < 2; half++) {
                const int m = m0 + wm * 32 + mi * 16 + g + half * 8;
                const int t = m & (T_SEQ - 1);
                const int b = m >> 11;
                const float v0 = c[mi][ni][half * 2 + 0];
                const float v1 = c[mi][ni][half * 2 + 1];
                const size_t base =
                    (((size_t)(b * NH + h) * T_SEQ) + t) * HS + d;
                if (z < 2) {
                    // fp32 Cody-Waite mod 2pi (fast-math-proof)
                    const float ang = (float)t * theta;
                    const float nq = floorf(ang * 0.15915494309f);
                    float r = fmaf(-nq, 6.28125f, ang);
                    r = fmaf(-nq, 1.9353072e-3f, r);
                    const float sn = __sinf(r);
                    const float cs = __cosf(r);
                    *(float2*)(out + base) =
                        make_float2(v0 * cs - v1 * sn, v1 * cs + v0 * sn);
                } else {
                    *(float2*)(out + base) = make_float2(v0, v1);
                }
            }
        }
    }
}

// ---------------------------------------------------------------------------
// Kernel B: tf32 mma flash attention.
// Block = 128 queries x 64-key tiles; 256 threads, 8 warps; each warp owns
// 16 full S rows. Smem pitch 68 (conflict-free fragment LDS). 2 blocks/SM.
// ---------------------------------------------------------------------------
#define FPAD 68
#define QT 128

__global__ __launch_bounds__(256, 2) void flash_attn4(float* __restrict__ out)
{
    extern __shared__ float sm[];
    float* Qs = sm;               // [128][FPAD]  Qs[q][d]    (tf32)
    float* Ks = Qs + QT * FPAD;   // [64][FPAD]   Ks[key][d]  (tf32)
    float* Vt = Ks + 64 * FPAD;   // [64][FPAD]   Vt[d][j]    (tf32, transposed)
    float* Ps = Vt + 64 * FPAD;   // [128][FPAD]  Ps[q][j]    (tf32)

    const int bh = blockIdx.y;                    // b*NH + h
    const int qi = (gridDim.x - 1) - blockIdx.x;  // heavy q-tiles first
    const int q0 = qi * QT;
    const int tid  = threadIdx.x;
    const int warp = tid >> 5;
    const int lane = tid & 31;
    const int g  = lane >> 2;
    const int tg = lane & 3;
    const int r0 = warp * 16 + g;                 // local S/O row (also +8)

    const float* __restrict__ qp = g_q + (size_t)bh * T_SEQ * HS;
    const float* __restrict__ kp = g_k + (size_t)bh * T_SEQ * HS;
    const float* __restrict__ vp = g_v + (size_t)bh * T_SEQ * HS;

    // Load Q tile (row-major, cvt to tf32): 128 rows x 64 d
#pragma unroll
    for (int i = 0; i < 8; i++) {
        const int f = tid + 256 * i;
        const int j = f >> 4;
        const int d4 = (f & 15) * 4;
        float4 v = *(const float4*)(qp + (size_t)(q0 + j) * HS + d4);
        uint4 u = make_uint4(f2tf32(v.x), f2tf32(v.y), f2tf32(v.z), f2tf32(v.w));
        *(uint4*)&Qs[j * FPAD + d4] = u;
    }

    float m[2] = {-INFINITY, -INFINITY};
    float l[2] = {0.f, 0.f};
    float co[8][4];
#pragma unroll
    for (int ni = 0; ni < 8; ni++)
#pragma unroll
        for (int c = 0; c < 4; c++) co[ni][c] = 0.f;

    // V-transpose loader mapping
    const int vj = tid & 63;
    const int vdb = (tid >> 6) * 16;

    const int ntiles = 2 * qi + 2;   // 64-key tiles covering [0, q0+128)
    for (int kt = 0; kt < ntiles; kt++) {
        const int k0 = kt * 64;
        const bool need_mask = (kt >= 2 * qi);
        // warps 0-3 (rows q0..q0+63) are fully masked on the last tile
        const bool active = !(kt == 2 * qi + 1 && warp < 4);

        __syncthreads();   // previous tile's Ks/Vt reads complete

        // K tile row-major (cvt tf32): 64 x 64
#pragma unroll
        for (int i = 0; i < 4; i++) {
            const int f = tid + 256 * i;
            const int j = f >> 4;
            const int d4 = (f & 15) * 4;
            float4 v = *(const float4*)(kp + (size_t)(k0 + j) * HS + d4);
            uint4 u = make_uint4(f2tf32(v.x), f2tf32(v.y), f2tf32(v.z), f2tf32(v.w));
            *(uint4*)&Ks[j * FPAD + d4] = u;
        }
        // V tile transposed -> Vt[d][j] (cvt tf32)
#pragma unroll
        for (int i = 0; i < 4; i++) {
            const int d = vdb + 4 * i;
            float4 v = *(const float4*)(vp + (size_t)(k0 + vj) * HS + d);
            Vt[(d + 0) * FPAD + vj] = f2tf32f(v.x);
            Vt[(d + 1) * FPAD + vj] = f2tf32f(v.y);
            Vt[(d + 2) * FPAD + vj] = f2tf32f(v.z);
            Vt[(d + 3) * FPAD + vj] = f2tf32f(v.w);
        }
        __syncthreads();

        if (active) {
            // ---- S = Q K^T : warp rows [warp*16, +16) x 64 cols ----
            float cs[8][4];
#pragma unroll
            for (int ni = 0; ni < 8; ni++)
#pragma unroll
                for (int c = 0; c < 4; c++) cs[ni][c] = 0.f;

#pragma unroll
            for (int k8 = 0; k8 < HS; k8 += 8) {
                const uint32_t a0 = __float_as_uint(Qs[r0 * FPAD + k8 + tg]);
                const uint32_t a1 = __float_as_uint(Qs[(r0 + 8) * FPAD + k8 + tg]);
                const uint32_t a2 = __float_as_uint(Qs[r0 * FPAD + k8 + tg + 4]);
                const uint32_t a3 = __float_as_uint(Qs[(r0 + 8) * FPAD + k8 + tg + 4]);
#pragma unroll
                for (int ni = 0; ni < 8; ni++) {
                    const uint32_t b0 = __float_as_uint(Ks[(ni * 8 + g) * FPAD + k8 + tg]);
                    const uint32_t b1 = __float_as_uint(Ks[(ni * 8 + g) * FPAD + k8 + tg + 4]);
                    MMA_TF32(cs[ni], a0, a1, a2, a3, b0, b1);
                }
            }

            // ---- scale + causal mask + online softmax ----
            float mt[2] = {-INFINITY, -INFINITY};
#pragma unroll
            for (int ni = 0; ni < 8; ni++) {
#pragma unroll
                for (int c = 0; c < 4; c++) {
                    float v = cs[ni][c] * 0.03125f;
                    if (need_mask) {
                        const int col = k0 + ni * 8 + 2 * tg + (c & 1);
                        const int row = q0 + r0 + 8 * (c >> 1);
                        if (col > row) v = -INFINITY;
                    }
                    cs[ni][c] = v;
                    mt[c >> 1] = fmaxf(mt[c >> 1], v);
                }
            }
#pragma unroll
            for (int h2 = 0; h2 < 2; h2++) {
                mt[h2] = fmaxf(mt[h2], __shfl_xor_sync(0xffffffffu, mt[h2], 1));
                mt[h2] = fmaxf(mt[h2], __shfl_xor_sync(0xffffffffu, mt[h2], 2));
            }
            float alpha[2];
#pragma unroll
            for (int h2 = 0; h2 < 2; h2++) {
                const float mnew = fmaxf(m[h2], mt[h2]);
                alpha[h2] = __expf(m[h2] - mnew);
                m[h2] = mnew;
            }
            float rs[2] = {0.f, 0.f};
#pragma unroll
            for (int ni = 0; ni < 8; ni++) {
#pragma unroll
                for (int c = 0; c < 4; c++) {
                    const float p = __expf(cs[ni][c] - m[c >> 1]);
                    cs[ni][c] = p;
                    rs[c >> 1] += p;
                }
            }
#pragma unroll
            for (int h2 = 0; h2 < 2; h2++) {
                rs[h2] += __shfl_xor_sync(0xffffffffu, rs[h2], 1);
                rs[h2] += __shfl_xor_sync(0xffffffffu, rs[h2], 2);
                l[h2] = l[h2] * alpha[h2] + rs[h2];
            }
#pragma unroll
            for (int ni = 0; ni < 8; ni++)
#pragma unroll
                for (int c = 0; c < 4; c++) co[ni][c] *= alpha[c >> 1];

            // ---- store P (tf32) to warp-private Ps rows ----
#pragma unroll
            for (int ni = 0; ni < 8; ni++) {
                float2 p0 = make_float2(f2tf32f(cs[ni][0]), f2tf32f(cs[ni][1]));
                float2 p1 = make_float2(f2tf32f(cs[ni][2]), f2tf32f(cs[ni][3]));
                *(float2*)&Ps[r0 * FPAD + ni * 8 + 2 * tg] = p0;
                *(float2*)&Ps[(r0 + 8) * FPAD + ni * 8 + 2 * tg] = p1;
            }
            __syncwarp();

            // ---- O += P V ----
#pragma unroll
            for (int j8 = 0; j8 < 64; j8 += 8) {
                const uint32_t a0 = __float_as_uint(Ps[r0 * FPAD + j8 + tg]);
                const uint32_t a1 = __float_as_uint(Ps[(r0 + 8) * FPAD + j8 + tg]);
                const uint32_t a2 = __float_as_uint(Ps[r0 * FPAD + j8 + tg + 4]);
                const uint32_t a3 = __float_as_uint(Ps[(r0 + 8) * FPAD + j8 + tg + 4]);
#pragma unroll
                for (int ni = 0; ni < 8; ni++) {
                    const uint32_t b0 = __float_as_uint(Vt[(ni * 8 + g) * FPAD + j8 + tg]);
                    const uint32_t b1 = __float_as_uint(Vt[(ni * 8 + g) * FPAD + j8 + tg + 4]);
                    MMA_TF32(co[ni], a0, a1, a2, a3, b0, b1);
                }
            }
        }
    }

    // ---- epilogue: O /= l, write [B,T,C] ----
    const int b = bh >> 4;
    const int h = bh & 15;
    const float inv0 = 1.f / l[0];
    const float inv1 = 1.f / l[1];
    const size_t base0 = ((size_t)(b * T_SEQ + q0 + r0)) * CDIM + h * HS;
    const size_t base1 = ((size_t)(b * T_SEQ + q0 + r0 + 8)) * CDIM + h * HS;
#pragma unroll
    for (int ni = 0; ni < 8; ni++) {
        const int d = ni * 8 + 2 * tg;
        *(float2*)(out + base0 + d) = make_float2(co[ni][0] * inv0, co[ni][1] * inv0);
        *(float2*)(out + base1 + d) = make_float2(co[ni][2] * inv1, co[ni][3] * inv1);
    }
}

// ---------------------------------------------------------------------------
extern "C" void kernel_launch(void* const* d_in, const int* in_sizes, int n_in,
                              void* d_out, int out_size)
{
    const float* x  = (const float*)d_in[0];
    const float* Wq = (const float*)d_in[1];
    const float* Wk = (const float*)d_in[2];
    const float* Wv = (const float*)d_in[3];
    float* out = (float*)d_out;

    const int gsmem = 2 * (GBM + GBN) * APITCH * (int)sizeof(float); // 55296
    cudaFuncSetAttribute(qkv_gemm_tf32,
                         cudaFuncAttributeMaxDynamicSharedMemorySize, gsmem);
    dim3 ggrid(CDIM / GBN, (BATCH * T_SEQ) / GBM, 3);
    qkv_gemm_tf32<<<ggrid, 256, gsmem>>>(x, Wq, Wk, Wv);

    const int fsmem = (2 * QT + 2 * 64) * FPAD * (int)sizeof(float); // 104448
    cudaFuncSetAttribute(flash_attn4,
                         cudaFuncAttributeMaxDynamicSharedMemorySize, fsmem);
    dim3 fgrid(T_SEQ / QT, BATCH * NH);
    flash_attn4<<<fgrid, 256, fsmem>>>(out);
}

// round 10
// speedup vs baseline: 5.2105x; 1.0788x over previous
#include <cuda_runtime.h>
#include <math.h>
#include <stdint.h>

// Problem constants
#define BATCH 2
#define T_SEQ 2048
#define CDIM  1024
#define NH    16
#define HS    64
#define QKV_ELEMS (BATCH * NH * T_SEQ * HS)   // 4 M floats = 16 MB each

// -2/1024 * ln(10000)
#define ROPE_COEF (-0.017988211f)

// Scratch (device globals — no allocation allowed in kernel_launch)
__device__ float g_q[QKV_ELEMS];
__device__ float g_k[QKV_ELEMS];
__device__ float g_v[QKV_ELEMS];

__device__ __forceinline__ uint32_t f2tf32(float f) {
    uint32_t r;
    asm("cvt.rna.tf32.f32 %0, %1;" : "=r"(r) : "f"(f));
    return r;
}
__device__ __forceinline__ float f2tf32f(float f) {
    return __uint_as_float(f2tf32(f));
}

#define MMA_TF32(C, A0, A1, A2, A3, B0, B1)                                    \
    asm volatile(                                                              \
        "mma.sync.aligned.m16n8k8.row.col.f32.tf32.tf32.f32 "                  \
        "{%0,%1,%2,%3}, {%4,%5,%6,%7}, {%8,%9}, {%0,%1,%2,%3};"                \
        : "+f"((C)[0]), "+f"((C)[1]), "+f"((C)[2]), "+f"((C)[3])               \
        : "r"(A0), "r"(A1), "r"(A2), "r"(A3), "r"(B0), "r"(B1))

// ldmatrix x4: four 8-row x 16B matrices; per-lane row addresses.
__device__ __forceinline__ void ldsm4(uint32_t* r, const float* p) {
    uint32_t addr = (uint32_t)__cvta_generic_to_shared(p);
    asm volatile(
        "ldmatrix.sync.aligned.m8n8.x4.shared.b16 {%0,%1,%2,%3}, [%4];"
        : "=r"(r[0]), "=r"(r[1]), "=r"(r[2]), "=r"(r[3]) : "r"(addr));
}

// ---------------------------------------------------------------------------
// Kernel A: out = x @ W^T via tf32 mma + LDSM, fused RoPE epilogue, [B,H,T,HS].
// Block tile 128x64, 8 warps of 32x32, BK=32, double-buffered dynamic smem.
// Grid: (16, 32, 3), Block: 256
// ---------------------------------------------------------------------------
#define GBM 128
#define GBN 64
#define GBK 32
#define APITCH 36

__global__ __launch_bounds__(256) void qkv_gemm_tf32(
    const float* __restrict__ x,
    const float* __restrict__ Wq,
    const float* __restrict__ Wk,
    const float* __restrict__ Wv)
{
    extern __shared__ float gsm[];
    float* As = gsm;                        // [2][GBM*APITCH]
    float* Bs = gsm + 2 * GBM * APITCH;     // [2][GBN*APITCH]

    const int z = blockIdx.z;
    const float* __restrict__ W = (z == 0) ? Wq : ((z == 1) ? Wk : Wv);
    float* __restrict__ out = (z == 0) ? g_q : ((z == 1) ? g_k : g_v);

    const int m0 = blockIdx.y * GBM;
    const int h  = blockIdx.x;
    const int n0 = h * GBN;

    const int tid  = threadIdx.x;
    const int warp = tid >> 5;
    const int lane = tid & 31;
    const int g    = lane >> 2;
    const int tg   = lane & 3;

    const int wm = warp >> 1;
    const int wn = warp & 1;

    // ldmatrix per-lane source rows/cols
    const int arow = wm * 32 + (lane & 7) + ((lane >> 3) & 1) * 8;
    const int acol = (lane >> 4) * 4;
    const int brow = wn * 32 + (lane & 7) + (lane >> 4) * 8;
    const int bcol = ((lane >> 3) & 1) * 4;

    // Loader mapping (BK=32)
    const int row_a = tid >> 1;           // 0..127
    const int ka    = (tid & 1) * 16;     // 0 or 16
    const int row_b = tid >> 2;           // 0..63
    const int kb    = (tid & 3) * 8;      // 0,8,16,24

    const float* xbase = x + (size_t)(m0 + row_a) * CDIM + ka;
    const float* wbase = W + (size_t)(n0 + row_b) * CDIM + kb;

    float4 ra[4], rb[2];

    auto ldg_stage = [&](int s) {
        const float* xp = xbase + s * GBK;
#pragma unroll
        for (int i = 0; i < 4; i++) ra[i] = *(const float4*)(xp + 4 * i);
        const float* wp = wbase + s * GBK;
#pragma unroll
        for (int i = 0; i < 2; i++) rb[i] = *(const float4*)(wp + 4 * i);
    };
    auto sts_stage = [&](int buf) {
        float* A = As + buf * GBM * APITCH + row_a * APITCH + ka;
#pragma unroll
        for (int i = 0; i < 4; i++) {
            float4 t = make_float4(f2tf32f(ra[i].x), f2tf32f(ra[i].y),
                                   f2tf32f(ra[i].z), f2tf32f(ra[i].w));
            *(float4*)(A + 4 * i) = t;
        }
        float* B = Bs + buf * GBN * APITCH + row_b * APITCH + kb;
#pragma unroll
        for (int i = 0; i < 2; i++) {
            float4 t = make_float4(f2tf32f(rb[i].x), f2tf32f(rb[i].y),
                                   f2tf32f(rb[i].z), f2tf32f(rb[i].w));
            *(float4*)(B + 4 * i) = t;
        }
    };

    float c[2][4][4];
#pragma unroll
    for (int mi = 0; mi < 2; mi++)
#pragma unroll
        for (int ni = 0; ni < 4; ni++)
#pragma unroll
            for (int r = 0; r < 4; r++) c[mi][ni][r] = 0.f;

    auto compute_stage = [&](int buf) {
        const float* A = As + buf * GBM * APITCH;
        const float* B = Bs + buf * GBN * APITCH;
#pragma unroll
        for (int k8 = 0; k8 < GBK; k8 += 8) {
            uint32_t a[2][4], b[2][4];
            ldsm4(a[0], &A[arow * APITCH + acol + k8]);
            ldsm4(a[1], &A[(arow + 16) * APITCH + acol + k8]);
            ldsm4(b[0], &B[brow * APITCH + bcol + k8]);
            ldsm4(b[1], &B[(brow + 16) * APITCH + bcol + k8]);
#pragma unroll
            for (int mi = 0; mi < 2; mi++)
#pragma unroll
                for (int nn = 0; nn < 2; nn++) {
                    MMA_TF32(c[mi][2 * nn],     a[mi][0], a[mi][1], a[mi][2],
                             a[mi][3], b[nn][0], b[nn][1]);
                    MMA_TF32(c[mi][2 * nn + 1], a[mi][0], a[mi][1], a[mi][2],
                             a[mi][3], b[nn][2], b[nn][3]);
                }
        }
    };

    const int stages = CDIM / GBK;   // 32
    ldg_stage(0);
    sts_stage(0);
    ldg_stage(1);
    __syncthreads();

    for (int s = 0; s < stages; s++) {
        compute_stage(s & 1);
        if (s + 1 < stages) {
            __syncthreads();
            sts_stage((s + 1) & 1);
            if (s + 2 < stages) ldg_stage(s + 2);
            __syncthreads();
        }
    }

    // ---- epilogue: RoPE (z<2) + store [B,H,T,HS] ----
#pragma unroll
    for (int mi = 0; mi < 2; mi++) {
#pragma unroll
        for (int ni = 0; ni < 4; ni++) {
            const int d = wn * 32 + ni * 8 + 2 * tg;
            float theta = 0.f;
            if (z < 2) theta = expf((float)(d >> 1) * ROPE_COEF);
#pragma unroll
            for (int half = 0; half < 2; half++) {
                const int m = m0 + wm * 32 + mi * 16 + g + half * 8;
                const int t = m & (T_SEQ - 1);
                const int b = m >> 11;
                const float v0 = c[mi][ni][half * 2 + 0];
                const float v1 = c[mi][ni][half * 2 + 1];
                const size_t base =
                    (((size_t)(b * NH + h) * T_SEQ) + t) * HS + d;
                if (z < 2) {
                    // fp32 Cody-Waite mod 2pi (fast-math-proof)
                    const float ang = (float)t * theta;
                    const float nq = floorf(ang * 0.15915494309f);
                    float r = fmaf(-nq, 6.28125f, ang);
                    r = fmaf(-nq, 1.9353072e-3f, r);
                    const float sn = __sinf(r);
                    const float cs = __cosf(r);
                    *(float2*)(out + base) =
                        make_float2(v0 * cs - v1 * sn, v1 * cs + v0 * sn);
                } else {
                    *(float2*)(out + base) = make_float2(v0, v1);
                }
            }
        }
    }
}

// ---------------------------------------------------------------------------
// Kernel B: tf32 mma flash attention with LDSM fragment loads.
// Block = 128 queries x 64-key tiles; 256 threads, 8 warps; each warp owns
// 16 full S rows. Smem pitch 68 (conflict-free LDSM phases). 2 blocks/SM.
// ---------------------------------------------------------------------------
#define FPAD 68
#define QT 128

__global__ __launch_bounds__(256, 2) void flash_attn4(float* __restrict__ out)
{
    extern __shared__ float sm[];
    float* Qs = sm;               // [128][FPAD]  Qs[q][d]    (tf32)
    float* Ks = Qs + QT * FPAD;   // [64][FPAD]   Ks[key][d]  (tf32)
    float* Vt = Ks + 64 * FPAD;   // [64][FPAD]   Vt[d][j]    (tf32, transposed)
    float* Ps = Vt + 64 * FPAD;   // [128][FPAD]  Ps[q][j]    (tf32)

    const int bh = blockIdx.y;                    // b*NH + h
    const int qi = (gridDim.x - 1) - blockIdx.x;  // heavy q-tiles first
    const int q0 = qi * QT;
    const int tid  = threadIdx.x;
    const int warp = tid >> 5;
    const int lane = tid & 31;
    const int g  = lane >> 2;
    const int tg = lane & 3;
    const int r0 = warp * 16 + g;                 // local S/O row (also +8)

    // ldmatrix per-lane rows/cols
    const int aRow = warp * 16 + (lane & 7) + ((lane >> 3) & 1) * 8;
    const int aCol = (lane >> 4) * 4;
    const int bRow = (lane & 7) + (lane >> 4) * 8;
    const int bCol = ((lane >> 3) & 1) * 4;

    const float* __restrict__ qp = g_q + (size_t)bh * T_SEQ * HS;
    const float* __restrict__ kp = g_k + (size_t)bh * T_SEQ * HS;
    const float* __restrict__ vp = g_v + (size_t)bh * T_SEQ * HS;

    // Load Q tile (row-major, cvt to tf32): 128 rows x 64 d
#pragma unroll
    for (int i = 0; i < 8; i++) {
        const int f = tid + 256 * i;
        const int j = f >> 4;
        const int d4 = (f & 15) * 4;
        float4 v = *(const float4*)(qp + (size_t)(q0 + j) * HS + d4);
        uint4 u = make_uint4(f2tf32(v.x), f2tf32(v.y), f2tf32(v.z), f2tf32(v.w));
        *(uint4*)&Qs[j * FPAD + d4] = u;
    }

    float m[2] = {-INFINITY, -INFINITY};
    float l[2] = {0.f, 0.f};
    float co[8][4];
#pragma unroll
    for (int ni = 0; ni < 8; ni++)
#pragma unroll
        for (int c = 0; c < 4; c++) co[ni][c] = 0.f;

    // V-transpose loader mapping
    const int vj = tid & 63;
    const int vdb = (tid >> 6) * 16;

    const int ntiles = 2 * qi + 2;   // 64-key tiles covering [0, q0+128)
    for (int kt = 0; kt < ntiles; kt++) {
        const int k0 = kt * 64;
        const bool need_mask = (kt >= 2 * qi);
        // warps 0-3 (rows q0..q0+63) are fully masked on the last tile
        const bool active = !(kt == 2 * qi + 1 && warp < 4);

        __syncthreads();   // previous tile's Ks/Vt reads complete

        // K tile row-major (cvt tf32): 64 x 64
#pragma unroll
        for (int i = 0; i < 4; i++) {
            const int f = tid + 256 * i;
            const int j = f >> 4;
            const int d4 = (f & 15) * 4;
            float4 v = *(const float4*)(kp + (size_t)(k0 + j) * HS + d4);
            uint4 u = make_uint4(f2tf32(v.x), f2tf32(v.y), f2tf32(v.z), f2tf32(v.w));
            *(uint4*)&Ks[j * FPAD + d4] = u;
        }
        // V tile transposed -> Vt[d][j] (cvt tf32)
#pragma unroll
        for (int i = 0; i < 4; i++) {
            const int d = vdb + 4 * i;
            float4 v = *(const float4*)(vp + (size_t)(k0 + vj) * HS + d);
            Vt[(d + 0) * FPAD + vj] = f2tf32f(v.x);
            Vt[(d + 1) * FPAD + vj] = f2tf32f(v.y);
            Vt[(d + 2) * FPAD + vj] = f2tf32f(v.z);
            Vt[(d + 3) * FPAD + vj] = f2tf32f(v.w);
        }
        __syncthreads();

        if (active) {
            // ---- S = Q K^T : warp rows [warp*16, +16) x 64 cols ----
            float cs[8][4];
#pragma unroll
            for (int ni = 0; ni < 8; ni++)
#pragma unroll
                for (int c = 0; c < 4; c++) cs[ni][c] = 0.f;

#pragma unroll
            for (int k8 = 0; k8 < HS; k8 += 8) {
                uint32_t a[4];
                ldsm4(a, &Qs[aRow * FPAD + aCol + k8]);
#pragma unroll
                for (int nn = 0; nn < 4; nn++) {
                    uint32_t b[4];
                    ldsm4(b, &Ks[(nn * 16 + bRow) * FPAD + bCol + k8]);
                    MMA_TF32(cs[2 * nn],     a[0], a[1], a[2], a[3], b[0], b[1]);
                    MMA_TF32(cs[2 * nn + 1], a[0], a[1], a[2], a[3], b[2], b[3]);
                }
            }

            // ---- scale + causal mask + online softmax ----
            float mt[2] = {-INFINITY, -INFINITY};
#pragma unroll
            for (int ni = 0; ni < 8; ni++) {
#pragma unroll
                for (int c = 0; c < 4; c++) {
                    float v = cs[ni][c] * 0.03125f;
                    if (need_mask) {
                        const int col = k0 + ni * 8 + 2 * tg + (c & 1);
                        const int row = q0 + r0 + 8 * (c >> 1);
                        if (col > row) v = -INFINITY;
                    }
                    cs[ni][c] = v;
                    mt[c >> 1] = fmaxf(mt[c >> 1], v);
                }
            }
#pragma unroll
            for (int h2 = 0; h2 < 2; h2++) {
                mt[h2] = fmaxf(mt[h2], __shfl_xor_sync(0xffffffffu, mt[h2], 1));
                mt[h2] = fmaxf(mt[h2], __shfl_xor_sync(0xffffffffu, mt[h2], 2));
            }
            float alpha[2];
#pragma unroll
            for (int h2 = 0; h2 < 2; h2++) {
                const float mnew = fmaxf(m[h2], mt[h2]);
                alpha[h2] = __expf(m[h2] - mnew);
                m[h2] = mnew;
            }
            float rs[2] = {0.f, 0.f};
#pragma unroll
            for (int ni = 0; ni < 8; ni++) {
#pragma unroll
                for (int c = 0; c < 4; c++) {
                    const float p = __expf(cs[ni][c] - m[c >> 1]);
                    cs[ni][c] = p;
                    rs[c >> 1] += p;
                }
            }
#pragma unroll
            for (int h2 = 0; h2 < 2; h2++) {
                rs[h2] += __shfl_xor_sync(0xffffffffu, rs[h2], 1);
                rs[h2] += __shfl_xor_sync(0xffffffffu, rs[h2], 2);
                l[h2] = l[h2] * alpha[h2] + rs[h2];
            }
#pragma unroll
            for (int ni = 0; ni < 8; ni++)
#pragma unroll
                for (int c = 0; c < 4; c++) co[ni][c] *= alpha[c >> 1];

            // ---- store P (tf32) to warp-private Ps rows ----
#pragma unroll
            for (int ni = 0; ni < 8; ni++) {
                float2 p0 = make_float2(f2tf32f(cs[ni][0]), f2tf32f(cs[ni][1]));
                float2 p1 = make_float2(f2tf32f(cs[ni][2]), f2tf32f(cs[ni][3]));
                *(float2*)&Ps[r0 * FPAD + ni * 8 + 2 * tg] = p0;
                *(float2*)&Ps[(r0 + 8) * FPAD + ni * 8 + 2 * tg] = p1;
            }
            __syncwarp();

            // ---- O += P V ----
#pragma unroll
            for (int j8 = 0; j8 < 64; j8 += 8) {
                uint32_t a[4];
                ldsm4(a, &Ps[aRow * FPAD + aCol + j8]);
#pragma unroll
                for (int nn = 0; nn < 4; nn++) {
                    uint32_t b[4];
                    ldsm4(b, &Vt[(nn * 16 + bRow) * FPAD + bCol + j8]);
                    MMA_TF32(co[2 * nn],     a[0], a[1], a[2], a[3], b[0], b[1]);
                    MMA_TF32(co[2 * nn + 1], a[0], a[1], a[2], a[3], b[2], b[3]);
                }
            }
        }
    }

    // ---- epilogue: O /= l, write [B,T,C] ----
    const int b = bh >> 4;
    const int h = bh & 15;
    const float inv0 = 1.f / l[0];
    const float inv1 = 1.f / l[1];
    const size_t base0 = ((size_t)(b * T_SEQ + q0 + r0)) * CDIM + h * HS;
    const size_t base1 = ((size_t)(b * T_SEQ + q0 + r0 + 8)) * CDIM + h * HS;
#pragma unroll
    for (int ni = 0; ni < 8; ni++) {
        const int d = ni * 8 + 2 * tg;
        *(float2*)(out + base0 + d) = make_float2(co[ni][0] * inv0, co[ni][1] * inv0);
        *(float2*)(out + base1 + d) = make_float2(co[ni][2] * inv1, co[ni][3] * inv1);
    }
}

// ---------------------------------------------------------------------------
extern "C" void kernel_launch(void* const* d_in, const int* in_sizes, int n_in,
                              void* d_out, int out_size)
{
    const float* x  = (const float*)d_in[0];
    const float* Wq = (const float*)d_in[1];
    const float* Wk = (const float*)d_in[2];
    const float* Wv = (const float*)d_in[3];
    float* out = (float*)d_out;

    const int gsmem = 2 * (GBM + GBN) * APITCH * (int)sizeof(float); // 55296
    cudaFuncSetAttribute(qkv_gemm_tf32,
                         cudaFuncAttributeMaxDynamicSharedMemorySize, gsmem);
    dim3 ggrid(CDIM / GBN, (BATCH * T_SEQ) / GBM, 3);
    qkv_gemm_tf32<<<ggrid, 256, gsmem>>>(x, Wq, Wk, Wv);

    const int fsmem = (2 * QT + 2 * 64) * FPAD * (int)sizeof(float); // 104448
    cudaFuncSetAttribute(flash_attn4,
                         cudaFuncAttributeMaxDynamicSharedMemorySize, fsmem);
    dim3 fgrid(T_SEQ / QT, BATCH * NH);
    flash_attn4<<<fgrid, 256, fsmem>>>(out);
}

// round 12
// speedup vs baseline: 5.4655x; 1.0489x over previous
#include <cuda_runtime.h>
#include <math.h>
#include <stdint.h>

// Problem constants
#define BATCH 2
#define T_SEQ 2048
#define CDIM  1024
#define NH    16
#define HS    64
#define QKV_ELEMS (BATCH * NH * T_SEQ * HS)   // 4 M floats = 16 MB each

// -2/1024 * ln(10000)
#define ROPE_COEF (-0.017988211f)

// Scratch (device globals — no allocation allowed in kernel_launch)
__device__ float g_q[QKV_ELEMS];
__device__ float g_k[QKV_ELEMS];
__device__ float g_v[QKV_ELEMS];

__device__ __forceinline__ uint32_t f2tf32(float f) {
    uint32_t r;
    asm("cvt.rna.tf32.f32 %0, %1;" : "=r"(r) : "f"(f));
    return r;
}
__device__ __forceinline__ float f2tf32f(float f) {
    return __uint_as_float(f2tf32(f));
}

#define MMA_TF32(C, A0, A1, A2, A3, B0, B1)                                    \
    asm volatile(                                                              \
        "mma.sync.aligned.m16n8k8.row.col.f32.tf32.tf32.f32 "                  \
        "{%0,%1,%2,%3}, {%4,%5,%6,%7}, {%8,%9}, {%0,%1,%2,%3};"                \
        : "+f"((C)[0]), "+f"((C)[1]), "+f"((C)[2]), "+f"((C)[3])               \
        : "r"(A0), "r"(A1), "r"(A2), "r"(A3), "r"(B0), "r"(B1))

// ldmatrix x4: four 8-row x 16B matrices; per-lane row addresses.
__device__ __forceinline__ void ldsm4(uint32_t* r, const float* p) {
    uint32_t addr = (uint32_t)__cvta_generic_to_shared(p);
    asm volatile(
        "ldmatrix.sync.aligned.m8n8.x4.shared.b16 {%0,%1,%2,%3}, [%4];"
        : "=r"(r[0]), "=r"(r[1]), "=r"(r[2]), "=r"(r[3]) : "r"(addr));
}

// cp.async helpers
__device__ __forceinline__ void cpa16(float* dst, const float* src) {
    uint32_t d = (uint32_t)__cvta_generic_to_shared(dst);
    asm volatile("cp.async.cg.shared.global [%0], [%1], 16;" :: "r"(d), "l"(src));
}
__device__ __forceinline__ void cpa4(float* dst, const float* src) {
    uint32_t d = (uint32_t)__cvta_generic_to_shared(dst);
    asm volatile("cp.async.ca.shared.global [%0], [%1], 4;" :: "r"(d), "l"(src));
}
#define CP_COMMIT() asm volatile("cp.async.commit_group;" ::: "memory")
#define CP_WAIT0()  asm volatile("cp.async.wait_group 0;" ::: "memory")

// ---------------------------------------------------------------------------
// Kernel A: out = x @ W^T via tf32 mma + LDSM, fused RoPE epilogue, [B,H,T,HS].
// (unchanged from R9/R10 — passed twice)
// ---------------------------------------------------------------------------
#define GBM 128
#define GBN 64
#define GBK 32
#define APITCH 36

__global__ __launch_bounds__(256) void qkv_gemm_tf32(
    const float* __restrict__ x,
    const float* __restrict__ Wq,
    const float* __restrict__ Wk,
    const float* __restrict__ Wv)
{
    extern __shared__ float gsm[];
    float* As = gsm;                        // [2][GBM*APITCH]
    float* Bs = gsm + 2 * GBM * APITCH;     // [2][GBN*APITCH]

    const int z = blockIdx.z;
    const float* __restrict__ W = (z == 0) ? Wq : ((z == 1) ? Wk : Wv);
    float* __restrict__ out = (z == 0) ? g_q : ((z == 1) ? g_k : g_v);

    const int m0 = blockIdx.y * GBM;
    const int h  = blockIdx.x;
    const int n0 = h * GBN;

    const int tid  = threadIdx.x;
    const int warp = tid >> 5;
    const int lane = tid & 31;
    const int g    = lane >> 2;
    const int tg   = lane & 3;

    const int wm = warp >> 1;
    const int wn = warp & 1;

    const int arow = wm * 32 + (lane & 7) + ((lane >> 3) & 1) * 8;
    const int acol = (lane >> 4) * 4;
    const int brow = wn * 32 + (lane & 7) + (lane >> 4) * 8;
    const int bcol = ((lane >> 3) & 1) * 4;

    const int row_a = tid >> 1;
    const int ka    = (tid & 1) * 16;
    const int row_b = tid >> 2;
    const int kb    = (tid & 3) * 8;

    const float* xbase = x + (size_t)(m0 + row_a) * CDIM + ka;
    const float* wbase = W + (size_t)(n0 + row_b) * CDIM + kb;

    float4 ra[4], rb[2];

    auto ldg_stage = [&](int s) {
        const float* xp = xbase + s * GBK;
#pragma unroll
        for (int i = 0; i < 4; i++) ra[i] = *(const float4*)(xp + 4 * i);
        const float* wp = wbase + s * GBK;
#pragma unroll
        for (int i = 0; i < 2; i++) rb[i] = *(const float4*)(wp + 4 * i);
    };
    auto sts_stage = [&](int buf) {
        float* A = As + buf * GBM * APITCH + row_a * APITCH + ka;
#pragma unroll
        for (int i = 0; i < 4; i++) {
            float4 t = make_float4(f2tf32f(ra[i].x), f2tf32f(ra[i].y),
                                   f2tf32f(ra[i].z), f2tf32f(ra[i].w));
            *(float4*)(A + 4 * i) = t;
        }
        float* B = Bs + buf * GBN * APITCH + row_b * APITCH + kb;
#pragma unroll
        for (int i = 0; i < 2; i++) {
            float4 t = make_float4(f2tf32f(rb[i].x), f2tf32f(rb[i].y),
                                   f2tf32f(rb[i].z), f2tf32f(rb[i].w));
            *(float4*)(B + 4 * i) = t;
        }
    };

    float c[2][4][4];
#pragma unroll
    for (int mi = 0; mi < 2; mi++)
#pragma unroll
        for (int ni = 0; ni < 4; ni++)
#pragma unroll
            for (int r = 0; r < 4; r++) c[mi][ni][r] = 0.f;

    auto compute_stage = [&](int buf) {
        const float* A = As + buf * GBM * APITCH;
        const float* B = Bs + buf * GBN * APITCH;
#pragma unroll
        for (int k8 = 0; k8 < GBK; k8 += 8) {
            uint32_t a[2][4], b[2][4];
            ldsm4(a[0], &A[arow * APITCH + acol + k8]);
            ldsm4(a[1], &A[(arow + 16) * APITCH + acol + k8]);
            ldsm4(b[0], &B[brow * APITCH + bcol + k8]);
            ldsm4(b[1], &B[(brow + 16) * APITCH + bcol + k8]);
#pragma unroll
            for (int mi = 0; mi < 2; mi++)
#pragma unroll
                for (int nn = 0; nn < 2; nn++) {
                    MMA_TF32(c[mi][2 * nn],     a[mi][0], a[mi][1], a[mi][2],
                             a[mi][3], b[nn][0], b[nn][1]);
                    MMA_TF32(c[mi][2 * nn + 1], a[mi][0], a[mi][1], a[mi][2],
                             a[mi][3], b[nn][2], b[nn][3]);
                }
        }
    };

    const int stages = CDIM / GBK;   // 32
    ldg_stage(0);
    sts_stage(0);
    ldg_stage(1);
    __syncthreads();

    for (int s = 0; s < stages; s++) {
        compute_stage(s & 1);
        if (s + 1 < stages) {
            __syncthreads();
            sts_stage((s + 1) & 1);
            if (s + 2 < stages) ldg_stage(s + 2);
            __syncthreads();
        }
    }

    // ---- epilogue: RoPE (z<2) + store [B,H,T,HS] ----
#pragma unroll
    for (int mi = 0; mi < 2; mi++) {
#pragma unroll
        for (int ni = 0; ni < 4; ni++) {
            const int d = wn * 32 + ni * 8 + 2 * tg;
            float theta = 0.f;
            if (z < 2) theta = expf((float)(d >> 1) * ROPE_COEF);
#pragma unroll
            for (int half = 0; half < 2; half++) {
                const int m = m0 + wm * 32 + mi * 16 + g + half * 8;
                const int t = m & (T_SEQ - 1);
                const int b = m >> 11;
                const float v0 = c[mi][ni][half * 2 + 0];
                const float v1 = c[mi][ni][half * 2 + 1];
                const size_t base =
                    (((size_t)(b * NH + h) * T_SEQ) + t) * HS + d;
                if (z < 2) {
                    // fp32 Cody-Waite mod 2pi (fast-math-proof)
                    const float ang = (float)t * theta;
                    const float nq = floorf(ang * 0.15915494309f);
                    float r = fmaf(-nq, 6.28125f, ang);
                    r = fmaf(-nq, 1.9353072e-3f, r);
                    const float sn = __sinf(r);
                    const float cs = __cosf(r);
                    *(float2*)(out + base) =
                        make_float2(v0 * cs - v1 * sn, v1 * cs + v0 * sn);
                } else {
                    *(float2*)(out + base) = make_float2(v0, v1);
                }
            }
        }
    }
}

// ---------------------------------------------------------------------------
// Kernel B: tf32 mma flash attention, cp.async double-buffered K/V,
// register-shuffle P transpose (no Ps smem).
// Block = 128 queries x 64-key tiles; 256 threads, 8 warps; warp owns 16 rows.
// smem: Qs[128][68] + K[2][64][68] + Vt[2][64][68] = 104448 B; 2 blocks/SM.
// ---------------------------------------------------------------------------
#define FPAD 68
#define QT 128
#define TILE68 (64 * FPAD)

__global__ __launch_bounds__(256, 2) void flash_attn6(float* __restrict__ out)
{
    extern __shared__ float sm[];
    float* Qs = sm;                       // [128][68]  Qs[q][d]   (tf32)
    float* Kb = Qs + QT * FPAD;           // [2][64][68] keys row-major
    float* Vb = Kb + 2 * TILE68;          // [2][64][68] Vt layout [d][j]

    const int bh = blockIdx.y;                    // b*NH + h
    const int qi = (gridDim.x - 1) - blockIdx.x;  // heavy q-tiles first
    const int q0 = qi * QT;
    const int tid  = threadIdx.x;
    const int warp = tid >> 5;
    const int lane = tid & 31;
    const int g  = lane >> 2;
    const int tg = lane & 3;
    const int r0 = warp * 16 + g;                 // local S/O row (also +8)

    // ldmatrix per-lane rows/cols (as R9)
    const int aRow = warp * 16 + (lane & 7) + ((lane >> 3) & 1) * 8;
    const int aCol = (lane >> 4) * 4;
    const int bRow = (lane & 7) + (lane >> 4) * 8;
    const int bCol = ((lane >> 3) & 1) * 4;

    // P shuffle-transpose source lanes
    const int src1 = (lane & 28) | (tg >> 1);   // (g<<2)|(tg>>1)
    const int src2 = src1 + 2;
    const bool odd = (tg & 1);

    const float* __restrict__ qp = g_q + (size_t)bh * T_SEQ * HS;
    const float* __restrict__ kp = g_k + (size_t)bh * T_SEQ * HS;
    const float* __restrict__ vp = g_v + (size_t)bh * T_SEQ * HS;

    // Load Q tile (row-major, cvt to tf32): 128 rows x 64 d
#pragma unroll
    for (int i = 0; i < 8; i++) {
        const int f = tid + 256 * i;
        const int j = f >> 4;
        const int d4 = (f & 15) * 4;
        float4 v = *(const float4*)(qp + (size_t)(q0 + j) * HS + d4);
        uint4 u = make_uint4(f2tf32(v.x), f2tf32(v.y), f2tf32(v.z), f2tf32(v.w));
        *(uint4*)&Qs[j * FPAD + d4] = u;
    }

    // ---- async tile loaders ----
    auto issue_tile = [&](int kt) {
        const int k0 = kt * 64;
        float* K = Kb + (kt & 1) * TILE68;
        float* V = Vb + (kt & 1) * TILE68;
#pragma unroll
        for (int i = 0; i < 4; i++) {
            const int f = tid + 256 * i;
            const int j = f >> 4;
            const int d4 = (f & 15) * 4;
            cpa16(&K[j * FPAD + d4], kp + (size_t)(k0 + j) * HS + d4);
        }
        const int d  = tid & 63;
        const int j0 = (tid >> 6) * 16;
#pragma unroll
        for (int i = 0; i < 16; i++)
            cpa4(&V[d * FPAD + j0 + i],
                 vp + (size_t)(k0 + j0 + i) * HS + d);
        CP_COMMIT();
    };
    auto cvt_tile = [&](int kt) {
        float* K = Kb + (kt & 1) * TILE68;
        float* V = Vb + (kt & 1) * TILE68;
#pragma unroll
        for (int i = 0; i < 4; i++) {
            const int f = tid + 256 * i;
            const int r = f >> 4;
            const int c4 = (f & 15) * 4;
            float4* pk = (float4*)&K[r * FPAD + c4];
            float4 kv = *pk;
            *pk = make_float4(f2tf32f(kv.x), f2tf32f(kv.y),
                              f2tf32f(kv.z), f2tf32f(kv.w));
            float4* pv = (float4*)&V[r * FPAD + c4];
            float4 vv = *pv;
            *pv = make_float4(f2tf32f(vv.x), f2tf32f(vv.y),
                              f2tf32f(vv.z), f2tf32f(vv.w));
        }
    };

    float m[2] = {-INFINITY, -INFINITY};
    float l[2] = {0.f, 0.f};
    float co[8][4];
#pragma unroll
    for (int ni = 0; ni < 8; ni++)
#pragma unroll
        for (int c = 0; c < 4; c++) co[ni][c] = 0.f;

    const int ntiles = 2 * qi + 2;   // 64-key tiles covering [0, q0+128)
    issue_tile(0);

    for (int kt = 0; kt < ntiles; kt++) {
        const int k0 = kt * 64;
        const bool need_mask = (kt >= 2 * qi);
        // warps 0-3 (rows q0..q0+63) are fully masked on the last tile
        const bool active = !(kt == 2 * qi + 1 && warp < 4);

        CP_WAIT0();          // this tile's cp.async groups complete
        __syncthreads();     // data visible + all warps done with kt-1 compute
        if (kt + 1 < ntiles) issue_tile(kt + 1);   // prefetch into other buf
        cvt_tile(kt);        // in-place RNA tf32 (thread-private chunks)
        __syncthreads();

        if (active) {
            const float* Ks = Kb + (kt & 1) * TILE68;
            const float* Vt = Vb + (kt & 1) * TILE68;

            // ---- S = Q K^T : warp rows [warp*16, +16) x 64 cols ----
            float cs[8][4];
#pragma unroll
            for (int ni = 0; ni < 8; ni++)
#pragma unroll
                for (int c = 0; c < 4; c++) cs[ni][c] = 0.f;

#pragma unroll
            for (int k8 = 0; k8 < HS; k8 += 8) {
                uint32_t a[4];
                ldsm4(a, &Qs[aRow * FPAD + aCol + k8]);
#pragma unroll
                for (int nn = 0; nn < 4; nn++) {
                    uint32_t b[4];
                    ldsm4(b, &Ks[(nn * 16 + bRow) * FPAD + bCol + k8]);
                    MMA_TF32(cs[2 * nn],     a[0], a[1], a[2], a[3], b[0], b[1]);
                    MMA_TF32(cs[2 * nn + 1], a[0], a[1], a[2], a[3], b[2], b[3]);
                }
            }

            // ---- scale + causal mask + online softmax ----
            float mt[2] = {-INFINITY, -INFINITY};
#pragma unroll
            for (int ni = 0; ni < 8; ni++) {
#pragma unroll
                for (int c = 0; c < 4; c++) {
                    float v = cs[ni][c] * 0.03125f;
                    if (need_mask) {
                        const int col = k0 + ni * 8 + 2 * tg + (c & 1);
                        const int row = q0 + r0 + 8 * (c >> 1);
                        if (col > row) v = -INFINITY;
                    }
                    cs[ni][c] = v;
                    mt[c >> 1] = fmaxf(mt[c >> 1], v);
                }
            }
#pragma unroll
            for (int h2 = 0; h2 < 2; h2++) {
                mt[h2] = fmaxf(mt[h2], __shfl_xor_sync(0xffffffffu, mt[h2], 1));
                mt[h2] = fmaxf(mt[h2], __shfl_xor_sync(0xffffffffu, mt[h2], 2));
            }
            float alpha[2];
#pragma unroll
            for (int h2 = 0; h2 < 2; h2++) {
                const float mnew = fmaxf(m[h2], mt[h2]);
                alpha[h2] = __expf(m[h2] - mnew);
                m[h2] = mnew;
            }
            float rs[2] = {0.f, 0.f};
#pragma unroll
            for (int ni = 0; ni < 8; ni++) {
#pragma unroll
                for (int c = 0; c < 4; c++) {
                    const float p = __expf(cs[ni][c] - m[c >> 1]);
                    cs[ni][c] = p;
                    rs[c >> 1] += p;
                }
            }
#pragma unroll
            for (int h2 = 0; h2 < 2; h2++) {
                rs[h2] += __shfl_xor_sync(0xffffffffu, rs[h2], 1);
                rs[h2] += __shfl_xor_sync(0xffffffffu, rs[h2], 2);
                l[h2] = l[h2] * alpha[h2] + rs[h2];
            }
#pragma unroll
            for (int ni = 0; ni < 8; ni++)
#pragma unroll
                for (int c = 0; c < 4; c++) co[ni][c] *= alpha[c >> 1];

            // ---- O += P V : P C-frag -> A-frag via warp shuffles ----
#pragma unroll
            for (int kk = 0; kk < 8; kk++) {
                const float x0 = __shfl_sync(0xffffffffu, cs[kk][0], src1);
                const float x1 = __shfl_sync(0xffffffffu, cs[kk][1], src1);
                const float x2 = __shfl_sync(0xffffffffu, cs[kk][2], src1);
                const float x3 = __shfl_sync(0xffffffffu, cs[kk][3], src1);
                const float y0 = __shfl_sync(0xffffffffu, cs[kk][0], src2);
                const float y1 = __shfl_sync(0xffffffffu, cs[kk][1], src2);
                const float y2 = __shfl_sync(0xffffffffu, cs[kk][2], src2);
                const float y3 = __shfl_sync(0xffffffffu, cs[kk][3], src2);
                const uint32_t a0 = f2tf32(odd ? x1 : x0);
                const uint32_t a1 = f2tf32(odd ? x3 : x2);
                const uint32_t a2 = f2tf32(odd ? y1 : y0);
                const uint32_t a3 = f2tf32(odd ? y3 : y2);
#pragma unroll
                for (int nn = 0; nn < 4; nn++) {
                    uint32_t b[4];
                    ldsm4(b, &Vt[(nn * 16 + bRow) * FPAD + bCol + 8 * kk]);
                    MMA_TF32(co[2 * nn],     a0, a1, a2, a3, b[0], b[1]);
                    MMA_TF32(co[2 * nn + 1], a0, a1, a2, a3, b[2], b[3]);
                }
            }
        }
    }

    // ---- epilogue: O /= l, write [B,T,C] ----
    const int b = bh >> 4;
    const int h = bh & 15;
    const float inv0 = 1.f / l[0];
    const float inv1 = 1.f / l[1];
    const size_t base0 = ((size_t)(b * T_SEQ + q0 + r0)) * CDIM + h * HS;
    const size_t base1 = ((size_t)(b * T_SEQ + q0 + r0 + 8)) * CDIM + h * HS;
#pragma unroll
    for (int ni = 0; ni < 8; ni++) {
        const int d = ni * 8 + 2 * tg;
        *(float2*)(out + base0 + d) = make_float2(co[ni][0] * inv0, co[ni][1] * inv0);
        *(float2*)(out + base1 + d) = make_float2(co[ni][2] * inv1, co[ni][3] * inv1);
    }
}

// ---------------------------------------------------------------------------
extern "C" void kernel_launch(void* const* d_in, const int* in_sizes, int n_in,
                              void* d_out, int out_size)
{
    const float* x  = (const float*)d_in[0];
    const float* Wq = (const float*)d_in[1];
    const float* Wk = (const float*)d_in[2];
    const float* Wv = (const float*)d_in[3];
    float* out = (float*)d_out;

    const int gsmem = 2 * (GBM + GBN) * APITCH * (int)sizeof(float); // 55296
    cudaFuncSetAttribute(qkv_gemm_tf32,
                         cudaFuncAttributeMaxDynamicSharedMemorySize, gsmem);
    dim3 ggrid(CDIM / GBN, (BATCH * T_SEQ) / GBM, 3);
    qkv_gemm_tf32<<<ggrid, 256, gsmem>>>(x, Wq, Wk, Wv);

    const int fsmem = (QT + 4 * 64) * FPAD * (int)sizeof(float);     // 104448
    cudaFuncSetAttribute(flash_attn6,
                         cudaFuncAttributeMaxDynamicSharedMemorySize, fsmem);
    dim3 fgrid(T_SEQ / QT, BATCH * NH);
    flash_attn6<<<fgrid, 256, fsmem>>>(out);
}

// round 13
// speedup vs baseline: 6.6148x; 1.2103x over previous
#include <cuda_runtime.h>
#include <math.h>
#include <stdint.h>

// Problem constants
#define BATCH 2
#define T_SEQ 2048
#define CDIM  1024
#define NH    16
#define HS    64
#define QKV_ELEMS (BATCH * NH * T_SEQ * HS)   // 4 M floats = 16 MB each

// -2/1024 * ln(10000)
#define ROPE_COEF (-0.017988211f)

// Scratch (device globals — no allocation allowed in kernel_launch)
__device__ float g_q[QKV_ELEMS];
__device__ float g_k[QKV_ELEMS];
__device__ float g_v[QKV_ELEMS];

__device__ __forceinline__ uint32_t f2tf32(float f) {
    uint32_t r;
    asm("cvt.rna.tf32.f32 %0, %1;" : "=r"(r) : "f"(f));
    return r;
}
__device__ __forceinline__ float f2tf32f(float f) {
    return __uint_as_float(f2tf32(f));
}
__device__ __forceinline__ uint32_t cvtfrag(uint32_t r) {
    return f2tf32(__uint_as_float(r));
}

#define MMA_TF32(C, A0, A1, A2, A3, B0, B1)                                    \
    asm volatile(                                                              \
        "mma.sync.aligned.m16n8k8.row.col.f32.tf32.tf32.f32 "                  \
        "{%0,%1,%2,%3}, {%4,%5,%6,%7}, {%8,%9}, {%0,%1,%2,%3};"                \
        : "+f"((C)[0]), "+f"((C)[1]), "+f"((C)[2]), "+f"((C)[3])               \
        : "r"(A0), "r"(A1), "r"(A2), "r"(A3), "r"(B0), "r"(B1))

// ldmatrix x4: four 8-row x 16B matrices; per-lane row addresses.
__device__ __forceinline__ void ldsm4(uint32_t* r, const float* p) {
    uint32_t addr = (uint32_t)__cvta_generic_to_shared(p);
    asm volatile(
        "ldmatrix.sync.aligned.m8n8.x4.shared.b16 {%0,%1,%2,%3}, [%4];"
        : "=r"(r[0]), "=r"(r[1]), "=r"(r[2]), "=r"(r[3]) : "r"(addr));
}

// cp.async helpers
__device__ __forceinline__ void cpa16(float* dst, const float* src) {
    uint32_t d = (uint32_t)__cvta_generic_to_shared(dst);
    asm volatile("cp.async.cg.shared.global [%0], [%1], 16;" :: "r"(d), "l"(src));
}
__device__ __forceinline__ void cpa4(float* dst, const float* src) {
    uint32_t d = (uint32_t)__cvta_generic_to_shared(dst);
    asm volatile("cp.async.ca.shared.global [%0], [%1], 4;" :: "r"(d), "l"(src));
}
#define CP_COMMIT() asm volatile("cp.async.commit_group;" ::: "memory")
#define CP_WAIT0()  asm volatile("cp.async.wait_group 0;" ::: "memory")
#define CP_WAIT1()  asm volatile("cp.async.wait_group 1;" ::: "memory")

// ---------------------------------------------------------------------------
// Kernel A: out = x @ W^T via tf32 mma, cp.async 3-stage pipeline,
// fused RoPE epilogue, [B,H,T,HS].
// Block tile 128x128 (two heads), 8 warps of 32x64, BK=32.
// Grid: (8, 32, 3), Block: 256.  smem = 3*(128+128)*36*4 = 110592 B.
// ---------------------------------------------------------------------------
#define GBM 128
#define GBN 128
#define GBK 32
#define APITCH 36
#define GTILE (GBM * APITCH)   // floats per A (or B) stage buffer

__global__ __launch_bounds__(256) void qkv_gemm_tf32(
    const float* __restrict__ x,
    const float* __restrict__ Wq,
    const float* __restrict__ Wk,
    const float* __restrict__ Wv)
{
    extern __shared__ float gsm[];
    float* As = gsm;                  // [3][GBM*APITCH]
    float* Bs = gsm + 3 * GTILE;      // [3][GBN*APITCH]

    const int z = blockIdx.z;
    const float* __restrict__ W = (z == 0) ? Wq : ((z == 1) ? Wk : Wv);
    float* __restrict__ out = (z == 0) ? g_q : ((z == 1) ? g_k : g_v);

    const int m0 = blockIdx.y * GBM;
    const int n0 = blockIdx.x * GBN;

    const int tid  = threadIdx.x;
    const int warp = tid >> 5;
    const int lane = tid & 31;
    const int g    = lane >> 2;
    const int tg   = lane & 3;

    const int wm = warp >> 1;          // 0..3 (32-row tile)
    const int wn = warp & 1;           // 0..1 (64-col tile)

    // ldmatrix per-lane source rows/cols
    const int arow = wm * 32 + (lane & 7) + ((lane >> 3) & 1) * 8;
    const int acol = (lane >> 4) * 4;
    const int brow = wn * 64 + (lane & 7) + (lane >> 4) * 8;
    const int bcol = ((lane >> 3) & 1) * 4;

    // cp.async loader mapping: 1024 float4 per tile each for A and B
    const int lrow = tid >> 3;             // 0..31 base row (x4 iters -> 128)
    const int lc4  = (tid & 7) * 4;        // 0..28

    auto issue_tile = [&](int s) {
        float* A = As + (s % 3) * GTILE;
        float* B = Bs + (s % 3) * GTILE;
        const int kofs = s * GBK + lc4;
#pragma unroll
        for (int i = 0; i < 4; i++) {
            const int r = lrow + 32 * i;
            cpa16(&A[r * APITCH + lc4], x + (size_t)(m0 + r) * CDIM + kofs);
            cpa16(&B[r * APITCH + lc4], W + (size_t)(n0 + r) * CDIM + kofs);
        }
    };

    float c[2][8][4];
#pragma unroll
    for (int mi = 0; mi < 2; mi++)
#pragma unroll
        for (int ni = 0; ni < 8; ni++)
#pragma unroll
            for (int r = 0; r < 4; r++) c[mi][ni][r] = 0.f;

    auto compute_stage = [&](int s) {
        const float* A = As + (s % 3) * GTILE;
        const float* B = Bs + (s % 3) * GTILE;
#pragma unroll
        for (int k8 = 0; k8 < GBK; k8 += 8) {
            uint32_t a[2][4], b[4][4];
            ldsm4(a[0], &A[arow * APITCH + acol + k8]);
            ldsm4(a[1], &A[(arow + 16) * APITCH + acol + k8]);
#pragma unroll
            for (int nn = 0; nn < 4; nn++)
                ldsm4(b[nn], &B[(brow + nn * 16) * APITCH + bcol + k8]);
            // RNA tf32 on fragments (same values as cvt-at-STS -> bit-identical)
#pragma unroll
            for (int mi = 0; mi < 2; mi++)
#pragma unroll
                for (int r = 0; r < 4; r++) a[mi][r] = cvtfrag(a[mi][r]);
#pragma unroll
            for (int nn = 0; nn < 4; nn++)
#pragma unroll
                for (int r = 0; r < 4; r++) b[nn][r] = cvtfrag(b[nn][r]);
#pragma unroll
            for (int mi = 0; mi < 2; mi++)
#pragma unroll
                for (int nn = 0; nn < 4; nn++) {
                    MMA_TF32(c[mi][2 * nn],     a[mi][0], a[mi][1], a[mi][2],
                             a[mi][3], b[nn][0], b[nn][1]);
                    MMA_TF32(c[mi][2 * nn + 1], a[mi][0], a[mi][1], a[mi][2],
                             a[mi][3], b[nn][2], b[nn][3]);
                }
        }
    };

    const int stages = CDIM / GBK;   // 32

    issue_tile(0); CP_COMMIT();
    issue_tile(1); CP_COMMIT();
    CP_WAIT1();                      // stage 0 arrived
    __syncthreads();

    for (int s = 0; s < stages; s++) {
        compute_stage(s);
        if (s + 2 < stages) issue_tile(s + 2);
        CP_COMMIT();                 // empty group at tail keeps FIFO count
        CP_WAIT1();                  // stage s+1 arrived (in-order retire)
        __syncthreads();             // buffer (s+2)%3 free for next issue
    }

    // ---- epilogue: RoPE (z<2) + store [B,H,T,HS] ----
#pragma unroll
    for (int mi = 0; mi < 2; mi++) {
#pragma unroll
        for (int ni = 0; ni < 8; ni++) {
            const int dg = wn * 64 + ni * 8 + 2 * tg;    // 0..127
            const int h  = blockIdx.x * 2 + (dg >> 6);
            const int d  = dg & 63;
            float theta = 0.f;
            if (z < 2) theta = expf((float)(d >> 1) * ROPE_COEF);
#pragma unroll
            for (int half = 0; half < 2; half++) {
                const int m = m0 + wm * 32 + mi * 16 + g + half * 8;
                const int t = m & (T_SEQ - 1);
                const int b = m >> 11;
                const float v0 = c[mi][ni][half * 2 + 0];
                const float v1 = c[mi][ni][half * 2 + 1];
                const size_t base =
                    (((size_t)(b * NH + h) * T_SEQ) + t) * HS + d;
                if (z < 2) {
                    // fp32 Cody-Waite mod 2pi (fast-math-proof)
                    const float ang = (float)t * theta;
                    const float nq = floorf(ang * 0.15915494309f);
                    float r = fmaf(-nq, 6.28125f, ang);
                    r = fmaf(-nq, 1.9353072e-3f, r);
                    const float sn = __sinf(r);
                    const float cs = __cosf(r);
                    *(float2*)(out + base) =
                        make_float2(v0 * cs - v1 * sn, v1 * cs + v0 * sn);
                } else {
                    *(float2*)(out + base) = make_float2(v0, v1);
                }
            }
        }
    }
}

// ---------------------------------------------------------------------------
// Kernel B: tf32 mma flash attention, cp.async double-buffered K/V,
// register-shuffle P transpose (no Ps smem).  (unchanged from R11)
// ---------------------------------------------------------------------------
#define FPAD 68
#define QT 128
#define TILE68 (64 * FPAD)

__global__ __launch_bounds__(256, 2) void flash_attn6(float* __restrict__ out)
{
    extern __shared__ float sm[];
    float* Qs = sm;                       // [128][68]  Qs[q][d]   (tf32)
    float* Kb = Qs + QT * FPAD;           // [2][64][68] keys row-major
    float* Vb = Kb + 2 * TILE68;          // [2][64][68] Vt layout [d][j]

    const int bh = blockIdx.y;                    // b*NH + h
    const int qi = (gridDim.x - 1) - blockIdx.x;  // heavy q-tiles first
    const int q0 = qi * QT;
    const int tid  = threadIdx.x;
    const int warp = tid >> 5;
    const int lane = tid & 31;
    const int g  = lane >> 2;
    const int tg = lane & 3;
    const int r0 = warp * 16 + g;                 // local S/O row (also +8)

    const int aRow = warp * 16 + (lane & 7) + ((lane >> 3) & 1) * 8;
    const int aCol = (lane >> 4) * 4;
    const int bRow = (lane & 7) + (lane >> 4) * 8;
    const int bCol = ((lane >> 3) & 1) * 4;

    // P shuffle-transpose source lanes
    const int src1 = (lane & 28) | (tg >> 1);
    const int src2 = src1 + 2;
    const bool odd = (tg & 1);

    const float* __restrict__ qp = g_q + (size_t)bh * T_SEQ * HS;
    const float* __restrict__ kp = g_k + (size_t)bh * T_SEQ * HS;
    const float* __restrict__ vp = g_v + (size_t)bh * T_SEQ * HS;

    // Load Q tile (row-major, cvt to tf32): 128 rows x 64 d
#pragma unroll
    for (int i = 0; i < 8; i++) {
        const int f = tid + 256 * i;
        const int j = f >> 4;
        const int d4 = (f & 15) * 4;
        float4 v = *(const float4*)(qp + (size_t)(q0 + j) * HS + d4);
        uint4 u = make_uint4(f2tf32(v.x), f2tf32(v.y), f2tf32(v.z), f2tf32(v.w));
        *(uint4*)&Qs[j * FPAD + d4] = u;
    }

    auto issue_tile = [&](int kt) {
        const int k0 = kt * 64;
        float* K = Kb + (kt & 1) * TILE68;
        float* V = Vb + (kt & 1) * TILE68;
#pragma unroll
        for (int i = 0; i < 4; i++) {
            const int f = tid + 256 * i;
            const int j = f >> 4;
            const int d4 = (f & 15) * 4;
            cpa16(&K[j * FPAD + d4], kp + (size_t)(k0 + j) * HS + d4);
        }
        const int d  = tid & 63;
        const int j0 = (tid >> 6) * 16;
#pragma unroll
        for (int i = 0; i < 16; i++)
            cpa4(&V[d * FPAD + j0 + i],
                 vp + (size_t)(k0 + j0 + i) * HS + d);
        CP_COMMIT();
    };
    auto cvt_tile = [&](int kt) {
        float* K = Kb + (kt & 1) * TILE68;
        float* V = Vb + (kt & 1) * TILE68;
#pragma unroll
        for (int i = 0; i < 4; i++) {
            const int f = tid + 256 * i;
            const int r = f >> 4;
            const int c4 = (f & 15) * 4;
            float4* pk = (float4*)&K[r * FPAD + c4];
            float4 kv = *pk;
            *pk = make_float4(f2tf32f(kv.x), f2tf32f(kv.y),
                              f2tf32f(kv.z), f2tf32f(kv.w));
            float4* pv = (float4*)&V[r * FPAD + c4];
            float4 vv = *pv;
            *pv = make_float4(f2tf32f(vv.x), f2tf32f(vv.y),
                              f2tf32f(vv.z), f2tf32f(vv.w));
        }
    };

    float m[2] = {-INFINITY, -INFINITY};
    float l[2] = {0.f, 0.f};
    float co[8][4];
#pragma unroll
    for (int ni = 0; ni < 8; ni++)
#pragma unroll
        for (int c = 0; c < 4; c++) co[ni][c] = 0.f;

    const int ntiles = 2 * qi + 2;
    issue_tile(0);

    for (int kt = 0; kt < ntiles; kt++) {
        const int k0 = kt * 64;
        const bool need_mask = (kt >= 2 * qi);
        const bool active = !(kt == 2 * qi + 1 && warp < 4);

        CP_WAIT0();
        __syncthreads();
        if (kt + 1 < ntiles) issue_tile(kt + 1);
        cvt_tile(kt);
        __syncthreads();

        if (active) {
            const float* Ks = Kb + (kt & 1) * TILE68;
            const float* Vt = Vb + (kt & 1) * TILE68;

            float cs[8][4];
#pragma unroll
            for (int ni = 0; ni < 8; ni++)
#pragma unroll
                for (int c = 0; c < 4; c++) cs[ni][c] = 0.f;

#pragma unroll
            for (int k8 = 0; k8 < HS; k8 += 8) {
                uint32_t a[4];
                ldsm4(a, &Qs[aRow * FPAD + aCol + k8]);
#pragma unroll
                for (int nn = 0; nn < 4; nn++) {
                    uint32_t b[4];
                    ldsm4(b, &Ks[(nn * 16 + bRow) * FPAD + bCol + k8]);
                    MMA_TF32(cs[2 * nn],     a[0], a[1], a[2], a[3], b[0], b[1]);
                    MMA_TF32(cs[2 * nn + 1], a[0], a[1], a[2], a[3], b[2], b[3]);
                }
            }

            float mt[2] = {-INFINITY, -INFINITY};
#pragma unroll
            for (int ni = 0; ni < 8; ni++) {
#pragma unroll
                for (int c = 0; c < 4; c++) {
                    float v = cs[ni][c] * 0.03125f;
                    if (need_mask) {
                        const int col = k0 + ni * 8 + 2 * tg + (c & 1);
                        const int row = q0 + r0 + 8 * (c >> 1);
                        if (col > row) v = -INFINITY;
                    }
                    cs[ni][c] = v;
                    mt[c >> 1] = fmaxf(mt[c >> 1], v);
                }
            }
#pragma unroll
            for (int h2 = 0; h2 < 2; h2++) {
                mt[h2] = fmaxf(mt[h2], __shfl_xor_sync(0xffffffffu, mt[h2], 1));
                mt[h2] = fmaxf(mt[h2], __shfl_xor_sync(0xffffffffu, mt[h2], 2));
            }
            float alpha[2];
#pragma unroll
            for (int h2 = 0; h2 < 2; h2++) {
                const float mnew = fmaxf(m[h2], mt[h2]);
                alpha[h2] = __expf(m[h2] - mnew);
                m[h2] = mnew;
            }
            float rs[2] = {0.f, 0.f};
#pragma unroll
            for (int ni = 0; ni < 8; ni++) {
#pragma unroll
                for (int c = 0; c < 4; c++) {
                    const float p = __expf(cs[ni][c] - m[c >> 1]);
                    cs[ni][c] = p;
                    rs[c >> 1] += p;
                }
            }
#pragma unroll
            for (int h2 = 0; h2 < 2; h2++) {
                rs[h2] += __shfl_xor_sync(0xffffffffu, rs[h2], 1);
                rs[h2] += __shfl_xor_sync(0xffffffffu, rs[h2], 2);
                l[h2] = l[h2] * alpha[h2] + rs[h2];
            }
#pragma unroll
            for (int ni = 0; ni < 8; ni++)
#pragma unroll
                for (int c = 0; c < 4; c++) co[ni][c] *= alpha[c >> 1];

            // ---- O += P V : P C-frag -> A-frag via warp shuffles ----
#pragma unroll
            for (int kk = 0; kk < 8; kk++) {
                const float x0 = __shfl_sync(0xffffffffu, cs[kk][0], src1);
                const float x1 = __shfl_sync(0xffffffffu, cs[kk][1], src1);
                const float x2 = __shfl_sync(0xffffffffu, cs[kk][2], src1);
                const float x3 = __shfl_sync(0xffffffffu, cs[kk][3], src1);
                const float y0 = __shfl_sync(0xffffffffu, cs[kk][0], src2);
                const float y1 = __shfl_sync(0xffffffffu, cs[kk][1], src2);
                const float y2 = __shfl_sync(0xffffffffu, cs[kk][2], src2);
                const float y3 = __shfl_sync(0xffffffffu, cs[kk][3], src2);
                const uint32_t a0 = f2tf32(odd ? x1 : x0);
                const uint32_t a1 = f2tf32(odd ? x3 : x2);
                const uint32_t a2 = f2tf32(odd ? y1 : y0);
                const uint32_t a3 = f2tf32(odd ? y3 : y2);
#pragma unroll
                for (int nn = 0; nn < 4; nn++) {
                    uint32_t b[4];
                    ldsm4(b, &Vt[(nn * 16 + bRow) * FPAD + bCol + 8 * kk]);
                    MMA_TF32(co[2 * nn],     a0, a1, a2, a3, b[0], b[1]);
                    MMA_TF32(co[2 * nn + 1], a0, a1, a2, a3, b[2], b[3]);
                }
            }
        }
    }

    // ---- epilogue: O /= l, write [B,T,C] ----
    const int b = bh >> 4;
    const int h = bh & 15;
    const float inv0 = 1.f / l[0];
    const float inv1 = 1.f / l[1];
    const size_t base0 = ((size_t)(b * T_SEQ + q0 + r0)) * CDIM + h * HS;
    const size_t base1 = ((size_t)(b * T_SEQ + q0 + r0 + 8)) * CDIM + h * HS;
#pragma unroll
    for (int ni = 0; ni < 8; ni++) {
        const int d = ni * 8 + 2 * tg;
        *(float2*)(out + base0 + d) = make_float2(co[ni][0] * inv0, co[ni][1] * inv0);
        *(float2*)(out + base1 + d) = make_float2(co[ni][2] * inv1, co[ni][3] * inv1);
    }
}

// ---------------------------------------------------------------------------
extern "C" void kernel_launch(void* const* d_in, const int* in_sizes, int n_in,
                              void* d_out, int out_size)
{
    const float* x  = (const float*)d_in[0];
    const float* Wq = (const float*)d_in[1];
    const float* Wk = (const float*)d_in[2];
    const float* Wv = (const float*)d_in[3];
    float* out = (float*)d_out;

    const int gsmem = 3 * (GBM + GBN) * APITCH * (int)sizeof(float); // 110592
    cudaFuncSetAttribute(qkv_gemm_tf32,
                         cudaFuncAttributeMaxDynamicSharedMemorySize, gsmem);
    dim3 ggrid(CDIM / GBN, (BATCH * T_SEQ) / GBM, 3);
    qkv_gemm_tf32<<<ggrid, 256, gsmem>>>(x, Wq, Wk, Wv);

    const int fsmem = (QT + 4 * 64) * FPAD * (int)sizeof(float);     // 104448
    cudaFuncSetAttribute(flash_attn6,
                         cudaFuncAttributeMaxDynamicSharedMemorySize, fsmem);
    dim3 fgrid(T_SEQ / QT, BATCH * NH);
    flash_attn6<<<fgrid, 256, fsmem>>>(out);
}

// round 14
// speedup vs baseline: 7.3936x; 1.1177x over previous
#include <cuda_runtime.h>
#include <math.h>
#include <stdint.h>

// Problem constants
#define BATCH 2
#define T_SEQ 2048
#define CDIM  1024
#define NH    16
#define HS    64
#define QKV_ELEMS (BATCH * NH * T_SEQ * HS)   // 4 M floats = 16 MB each

// -2/1024 * ln(10000)
#define ROPE_COEF (-0.017988211f)

// Scratch (device globals — no allocation allowed in kernel_launch)
__device__ float g_q[QKV_ELEMS];
__device__ float g_k[QKV_ELEMS];
__device__ float g_v[QKV_ELEMS];
__device__ float g_x[BATCH * T_SEQ * CDIM];   // tf32-rounded x
__device__ float g_w[3 * CDIM * CDIM];        // tf32-rounded Wq|Wk|Wv

__device__ __forceinline__ uint32_t f2tf32(float f) {
    uint32_t r;
    asm("cvt.rna.tf32.f32 %0, %1;" : "=r"(r) : "f"(f));
    return r;
}
__device__ __forceinline__ float f2tf32f(float f) {
    return __uint_as_float(f2tf32(f));
}

#define MMA_TF32(C, A0, A1, A2, A3, B0, B1)                                    \
    asm volatile(                                                              \
        "mma.sync.aligned.m16n8k8.row.col.f32.tf32.tf32.f32 "                  \
        "{%0,%1,%2,%3}, {%4,%5,%6,%7}, {%8,%9}, {%0,%1,%2,%3};"                \
        : "+f"((C)[0]), "+f"((C)[1]), "+f"((C)[2]), "+f"((C)[3])               \
        : "r"(A0), "r"(A1), "r"(A2), "r"(A3), "r"(B0), "r"(B1))

// ldmatrix x4: four 8-row x 16B matrices; per-lane row addresses.
__device__ __forceinline__ void ldsm4(uint32_t* r, const float* p) {
    uint32_t addr = (uint32_t)__cvta_generic_to_shared(p);
    asm volatile(
        "ldmatrix.sync.aligned.m8n8.x4.shared.b16 {%0,%1,%2,%3}, [%4];"
        : "=r"(r[0]), "=r"(r[1]), "=r"(r[2]), "=r"(r[3]) : "r"(addr));
}

// cp.async helpers
__device__ __forceinline__ void cpa16(float* dst, const float* src) {
    uint32_t d = (uint32_t)__cvta_generic_to_shared(dst);
    asm volatile("cp.async.cg.shared.global [%0], [%1], 16;" :: "r"(d), "l"(src));
}
__device__ __forceinline__ void cpa4(float* dst, const float* src) {
    uint32_t d = (uint32_t)__cvta_generic_to_shared(dst);
    asm volatile("cp.async.ca.shared.global [%0], [%1], 4;" :: "r"(d), "l"(src));
}
#define CP_COMMIT() asm volatile("cp.async.commit_group;" ::: "memory")
#define CP_WAIT0()  asm volatile("cp.async.wait_group 0;" ::: "memory")
#define CP_WAIT1()  asm volatile("cp.async.wait_group 1;" ::: "memory")

// ---------------------------------------------------------------------------
// Kernel 0: pre-round x and W to RNA tf32 (hoists all input cvt out of GEMM).
// ---------------------------------------------------------------------------
#define NX4 (BATCH * T_SEQ * CDIM / 4)   // 1 M float4
#define NW4 (CDIM * CDIM / 4)            // 256 K float4 per matrix

__global__ __launch_bounds__(256) void cvt_inputs(
    const float* __restrict__ x,
    const float* __restrict__ Wq,
    const float* __restrict__ Wk,
    const float* __restrict__ Wv)
{
    const int total = NX4 + 3 * NW4;
    for (int idx = blockIdx.x * 256 + threadIdx.x; idx < total;
         idx += gridDim.x * 256) {
        const float4* src;
        float4* dst;
        if (idx < NX4) {
            src = (const float4*)x + idx;
            dst = (float4*)g_x + idx;
        } else {
            const int r = idx - NX4;
            const int w = r / NW4;
            const int o = r - w * NW4;
            const float* W = (w == 0) ? Wq : ((w == 1) ? Wk : Wv);
            src = (const float4*)W + o;
            dst = (float4*)g_w + (size_t)w * NW4 + o;
        }
        float4 v = *src;
        *dst = make_float4(f2tf32f(v.x), f2tf32f(v.y),
                           f2tf32f(v.z), f2tf32f(v.w));
    }
}

// ---------------------------------------------------------------------------
// Kernel A: out = x @ W^T via tf32 mma, cp.async 3-stage pipeline,
// fused RoPE epilogue, outputs tf32-rounded [B,H,T,HS].
// Block tile 128x128 (two heads), 8 warps of 32x64, BK=32.
// Grid: (8, 32, 3), Block: 256.  smem = 3*(128+128)*36*4 = 110592 B.
// ---------------------------------------------------------------------------
#define GBM 128
#define GBN 128
#define GBK 32
#define APITCH 36
#define GTILE (GBM * APITCH)   // floats per A (or B) stage buffer

__global__ __launch_bounds__(256) void qkv_gemm_tf32()
{
    extern __shared__ float gsm[];
    float* As = gsm;                  // [3][GBM*APITCH]
    float* Bs = gsm + 3 * GTILE;      // [3][GBN*APITCH]

    const int z = blockIdx.z;
    const float* __restrict__ X = g_x;
    const float* __restrict__ W = g_w + (size_t)z * CDIM * CDIM;
    float* __restrict__ out = (z == 0) ? g_q : ((z == 1) ? g_k : g_v);

    const int m0 = blockIdx.y * GBM;
    const int n0 = blockIdx.x * GBN;

    const int tid  = threadIdx.x;
    const int warp = tid >> 5;
    const int lane = tid & 31;
    const int g    = lane >> 2;
    const int tg   = lane & 3;

    const int wm = warp >> 1;          // 0..3 (32-row tile)
    const int wn = warp & 1;           // 0..1 (64-col tile)

    // ldmatrix per-lane source rows/cols
    const int arow = wm * 32 + (lane & 7) + ((lane >> 3) & 1) * 8;
    const int acol = (lane >> 4) * 4;
    const int brow = wn * 64 + (lane & 7) + (lane >> 4) * 8;
    const int bcol = ((lane >> 3) & 1) * 4;

    // cp.async loader mapping: 1024 float4 per tile each for A and B
    const int lrow = tid >> 3;             // 0..31 base row (x4 iters -> 128)
    const int lc4  = (tid & 7) * 4;        // 0..28

    auto issue_tile = [&](int s) {
        float* A = As + (s % 3) * GTILE;
        float* B = Bs + (s % 3) * GTILE;
        const int kofs = s * GBK + lc4;
#pragma unroll
        for (int i = 0; i < 4; i++) {
            const int r = lrow + 32 * i;
            cpa16(&A[r * APITCH + lc4], X + (size_t)(m0 + r) * CDIM + kofs);
            cpa16(&B[r * APITCH + lc4], W + (size_t)(n0 + r) * CDIM + kofs);
        }
    };

    float c[2][8][4];
#pragma unroll
    for (int mi = 0; mi < 2; mi++)
#pragma unroll
        for (int ni = 0; ni < 8; ni++)
#pragma unroll
            for (int r = 0; r < 4; r++) c[mi][ni][r] = 0.f;

    auto compute_stage = [&](int s) {
        const float* A = As + (s % 3) * GTILE;
        const float* B = Bs + (s % 3) * GTILE;
#pragma unroll
        for (int k8 = 0; k8 < GBK; k8 += 8) {
            uint32_t a[2][4], b[4][4];
            ldsm4(a[0], &A[arow * APITCH + acol + k8]);
            ldsm4(a[1], &A[(arow + 16) * APITCH + acol + k8]);
#pragma unroll
            for (int nn = 0; nn < 4; nn++)
                ldsm4(b[nn], &B[(brow + nn * 16) * APITCH + bcol + k8]);
            // data pre-rounded to tf32 by cvt_inputs — no cvt here
#pragma unroll
            for (int mi = 0; mi < 2; mi++)
#pragma unroll
                for (int nn = 0; nn < 4; nn++) {
                    MMA_TF32(c[mi][2 * nn],     a[mi][0], a[mi][1], a[mi][2],
                             a[mi][3], b[nn][0], b[nn][1]);
                    MMA_TF32(c[mi][2 * nn + 1], a[mi][0], a[mi][1], a[mi][2],
                             a[mi][3], b[nn][2], b[nn][3]);
                }
        }
    };

    const int stages = CDIM / GBK;   // 32

    issue_tile(0); CP_COMMIT();
    issue_tile(1); CP_COMMIT();
    CP_WAIT1();                      // stage 0 arrived
    __syncthreads();

    for (int s = 0; s < stages; s++) {
        compute_stage(s);
        if (s + 2 < stages) issue_tile(s + 2);
        CP_COMMIT();                 // empty group at tail keeps FIFO count
        CP_WAIT1();                  // stage s+1 arrived (in-order retire)
        __syncthreads();             // buffer (s+2)%3 free for next issue
    }

    // ---- epilogue: RoPE (z<2) + tf32-round + store [B,H,T,HS] ----
#pragma unroll
    for (int mi = 0; mi < 2; mi++) {
#pragma unroll
        for (int ni = 0; ni < 8; ni++) {
            const int dg = wn * 64 + ni * 8 + 2 * tg;    // 0..127
            const int h  = blockIdx.x * 2 + (dg >> 6);
            const int d  = dg & 63;
            float theta = 0.f;
            if (z < 2) theta = expf((float)(d >> 1) * ROPE_COEF);
#pragma unroll
            for (int half = 0; half < 2; half++) {
                const int m = m0 + wm * 32 + mi * 16 + g + half * 8;
                const int t = m & (T_SEQ - 1);
                const int b = m >> 11;
                const float v0 = c[mi][ni][half * 2 + 0];
                const float v1 = c[mi][ni][half * 2 + 1];
                const size_t base =
                    (((size_t)(b * NH + h) * T_SEQ) + t) * HS + d;
                if (z < 2) {
                    // fp32 Cody-Waite mod 2pi (fast-math-proof)
                    const float ang = (float)t * theta;
                    const float nq = floorf(ang * 0.15915494309f);
                    float r = fmaf(-nq, 6.28125f, ang);
                    r = fmaf(-nq, 1.9353072e-3f, r);
                    const float sn = __sinf(r);
                    const float cs = __cosf(r);
                    *(float2*)(out + base) =
                        make_float2(f2tf32f(v0 * cs - v1 * sn),
                                    f2tf32f(v1 * cs + v0 * sn));
                } else {
                    *(float2*)(out + base) =
                        make_float2(f2tf32f(v0), f2tf32f(v1));
                }
            }
        }
    }
}

// ---------------------------------------------------------------------------
// Kernel B: tf32 mma flash attention, cp.async double-buffered K/V (inputs
// pre-rounded to tf32), register-shuffle P transpose. One barrier per tile.
// ---------------------------------------------------------------------------
#define FPAD 68
#define QT 128
#define TILE68 (64 * FPAD)

__global__ __launch_bounds__(256, 2) void flash_attn7(float* __restrict__ out)
{
    extern __shared__ float sm[];
    float* Qs = sm;                       // [128][68]  Qs[q][d]   (tf32)
    float* Kb = Qs + QT * FPAD;           // [2][64][68] keys row-major
    float* Vb = Kb + 2 * TILE68;          // [2][64][68] Vt layout [d][j]

    const int bh = blockIdx.y;                    // b*NH + h
    const int qi = (gridDim.x - 1) - blockIdx.x;  // heavy q-tiles first
    const int q0 = qi * QT;
    const int tid  = threadIdx.x;
    const int warp = tid >> 5;
    const int lane = tid & 31;
    const int g  = lane >> 2;
    const int tg = lane & 3;
    const int r0 = warp * 16 + g;                 // local S/O row (also +8)

    const int aRow = warp * 16 + (lane & 7) + ((lane >> 3) & 1) * 8;
    const int aCol = (lane >> 4) * 4;
    const int bRow = (lane & 7) + (lane >> 4) * 8;
    const int bCol = ((lane >> 3) & 1) * 4;

    // P shuffle-transpose source lanes
    const int src1 = (lane & 28) | (tg >> 1);
    const int src2 = src1 + 2;
    const bool odd = (tg & 1);

    const float* __restrict__ qp = g_q + (size_t)bh * T_SEQ * HS;
    const float* __restrict__ kp = g_k + (size_t)bh * T_SEQ * HS;
    const float* __restrict__ vp = g_v + (size_t)bh * T_SEQ * HS;

    // Load Q tile (already tf32-rounded): plain copy, 128 rows x 64 d
#pragma unroll
    for (int i = 0; i < 8; i++) {
        const int f = tid + 256 * i;
        const int j = f >> 4;
        const int d4 = (f & 15) * 4;
        *(float4*)&Qs[j * FPAD + d4] =
            *(const float4*)(qp + (size_t)(q0 + j) * HS + d4);
    }

    auto issue_tile = [&](int kt) {
        const int k0 = kt * 64;
        float* K = Kb + (kt & 1) * TILE68;
        float* V = Vb + (kt & 1) * TILE68;
#pragma unroll
        for (int i = 0; i < 4; i++) {
            const int f = tid + 256 * i;
            const int j = f >> 4;
            const int d4 = (f & 15) * 4;
            cpa16(&K[j * FPAD + d4], kp + (size_t)(k0 + j) * HS + d4);
        }
        const int d  = tid & 63;
        const int j0 = (tid >> 6) * 16;
#pragma unroll
        for (int i = 0; i < 16; i++)
            cpa4(&V[d * FPAD + j0 + i],
                 vp + (size_t)(k0 + j0 + i) * HS + d);
        CP_COMMIT();
    };

    float m[2] = {-INFINITY, -INFINITY};
    float l[2] = {0.f, 0.f};
    float co[8][4];
#pragma unroll
    for (int ni = 0; ni < 8; ni++)
#pragma unroll
        for (int c = 0; c < 4; c++) co[ni][c] = 0.f;

    const int ntiles = 2 * qi + 2;
    issue_tile(0);

    for (int kt = 0; kt < ntiles; kt++) {
        const int k0 = kt * 64;
        const bool need_mask = (kt >= 2 * qi);
        const bool active = !(kt == 2 * qi + 1 && warp < 4);

        CP_WAIT0();          // tile kt arrived (only outstanding group)
        __syncthreads();     // visible to all; prev compute done
        if (kt + 1 < ntiles) issue_tile(kt + 1);   // prefetch other buffer

        if (active) {
            const float* Ks = Kb + (kt & 1) * TILE68;
            const float* Vt = Vb + (kt & 1) * TILE68;

            float cs[8][4];
#pragma unroll
            for (int ni = 0; ni < 8; ni++)
#pragma unroll
                for (int c = 0; c < 4; c++) cs[ni][c] = 0.f;

#pragma unroll
            for (int k8 = 0; k8 < HS; k8 += 8) {
                uint32_t a[4];
                ldsm4(a, &Qs[aRow * FPAD + aCol + k8]);
#pragma unroll
                for (int nn = 0; nn < 4; nn++) {
                    uint32_t b[4];
                    ldsm4(b, &Ks[(nn * 16 + bRow) * FPAD + bCol + k8]);
                    MMA_TF32(cs[2 * nn],     a[0], a[1], a[2], a[3], b[0], b[1]);
                    MMA_TF32(cs[2 * nn + 1], a[0], a[1], a[2], a[3], b[2], b[3]);
                }
            }

            float mt[2] = {-INFINITY, -INFINITY};
#pragma unroll
            for (int ni = 0; ni < 8; ni++) {
#pragma unroll
                for (int c = 0; c < 4; c++) {
                    float v = cs[ni][c] * 0.03125f;
                    if (need_mask) {
                        const int col = k0 + ni * 8 + 2 * tg + (c & 1);
                        const int row = q0 + r0 + 8 * (c >> 1);
                        if (col > row) v = -INFINITY;
                    }
                    cs[ni][c] = v;
                    mt[c >> 1] = fmaxf(mt[c >> 1], v);
                }
            }
#pragma unroll
            for (int h2 = 0; h2 < 2; h2++) {
                mt[h2] = fmaxf(mt[h2], __shfl_xor_sync(0xffffffffu, mt[h2], 1));
                mt[h2] = fmaxf(mt[h2], __shfl_xor_sync(0xffffffffu, mt[h2], 2));
            }
            float alpha[2];
#pragma unroll
            for (int h2 = 0; h2 < 2; h2++) {
                const float mnew = fmaxf(m[h2], mt[h2]);
                alpha[h2] = __expf(m[h2] - mnew);
                m[h2] = mnew;
            }
            float rs[2] = {0.f, 0.f};
#pragma unroll
            for (int ni = 0; ni < 8; ni++) {
#pragma unroll
                for (int c = 0; c < 4; c++) {
                    const float p = __expf(cs[ni][c] - m[c >> 1]);
                    cs[ni][c] = p;
                    rs[c >> 1] += p;
                }
            }
#pragma unroll
            for (int h2 = 0; h2 < 2; h2++) {
                rs[h2] += __shfl_xor_sync(0xffffffffu, rs[h2], 1);
                rs[h2] += __shfl_xor_sync(0xffffffffu, rs[h2], 2);
                l[h2] = l[h2] * alpha[h2] + rs[h2];
            }
#pragma unroll
            for (int ni = 0; ni < 8; ni++)
#pragma unroll
                for (int c = 0; c < 4; c++) co[ni][c] *= alpha[c >> 1];

            // ---- O += P V : P C-frag -> A-frag via warp shuffles ----
#pragma unroll
            for (int kk = 0; kk < 8; kk++) {
                const float x0 = __shfl_sync(0xffffffffu, cs[kk][0], src1);
                const float x1 = __shfl_sync(0xffffffffu, cs[kk][1], src1);
                const float x2 = __shfl_sync(0xffffffffu, cs[kk][2], src1);
                const float x3 = __shfl_sync(0xffffffffu, cs[kk][3], src1);
                const float y0 = __shfl_sync(0xffffffffu, cs[kk][0], src2);
                const float y1 = __shfl_sync(0xffffffffu, cs[kk][1], src2);
                const float y2 = __shfl_sync(0xffffffffu, cs[kk][2], src2);
                const float y3 = __shfl_sync(0xffffffffu, cs[kk][3], src2);
                const uint32_t a0 = f2tf32(odd ? x1 : x0);
                const uint32_t a1 = f2tf32(odd ? x3 : x2);
                const uint32_t a2 = f2tf32(odd ? y1 : y0);
                const uint32_t a3 = f2tf32(odd ? y3 : y2);
#pragma unroll
                for (int nn = 0; nn < 4; nn++) {
                    uint32_t b[4];
                    ldsm4(b, &Vt[(nn * 16 + bRow) * FPAD + bCol + 8 * kk]);
                    MMA_TF32(co[2 * nn],     a0, a1, a2, a3, b[0], b[1]);
                    MMA_TF32(co[2 * nn + 1], a0, a1, a2, a3, b[2], b[3]);
                }
            }
        }
    }

    // ---- epilogue: O /= l, write [B,T,C] ----
    const int b = bh >> 4;
    const int h = bh & 15;
    const float inv0 = 1.f / l[0];
    const float inv1 = 1.f / l[1];
    const size_t base0 = ((size_t)(b * T_SEQ + q0 + r0)) * CDIM + h * HS;
    const size_t base1 = ((size_t)(b * T_SEQ + q0 + r0 + 8)) * CDIM + h * HS;
#pragma unroll
    for (int ni = 0; ni < 8; ni++) {
        const int d = ni * 8 + 2 * tg;
        *(float2*)(out + base0 + d) = make_float2(co[ni][0] * inv0, co[ni][1] * inv0);
        *(float2*)(out + base1 + d) = make_float2(co[ni][2] * inv1, co[ni][3] * inv1);
    }
}

// ---------------------------------------------------------------------------
extern "C" void kernel_launch(void* const* d_in, const int* in_sizes, int n_in,
                              void* d_out, int out_size)
{
    const float* x  = (const float*)d_in[0];
    const float* Wq = (const float*)d_in[1];
    const float* Wk = (const float*)d_in[2];
    const float* Wv = (const float*)d_in[3];
    float* out = (float*)d_out;

    cvt_inputs<<<1024, 256>>>(x, Wq, Wk, Wv);

    const int gsmem = 3 * (GBM + GBN) * APITCH * (int)sizeof(float); // 110592
    cudaFuncSetAttribute(qkv_gemm_tf32,
                         cudaFuncAttributeMaxDynamicSharedMemorySize, gsmem);
    dim3 ggrid(CDIM / GBN, (BATCH * T_SEQ) / GBM, 3);
    qkv_gemm_tf32<<<ggrid, 256, gsmem>>>();

    const int fsmem = (QT + 4 * 64) * FPAD * (int)sizeof(float);     // 104448
    cudaFuncSetAttribute(flash_attn7,
                         cudaFuncAttributeMaxDynamicSharedMemorySize, fsmem);
    dim3 fgrid(T_SEQ / QT, BATCH * NH);
    flash_attn7<<<fgrid, 256, fsmem>>>(out);
}